// round 8
// baseline (speedup 1.0000x reference)
#include <cuda_runtime.h>
#include <math.h>
#include <cstddef>
#include <cstdint>

// ---------------- constants ----------------
#define BN_SC 0.9999950000374997f   // 1/sqrt(1+1e-5) as float
#define NB 8
#define NC 64
#define NH_ 8
#define HW128 128
#define NS 126
#define NIMG (NB*NC)                 // 512
#define ATTN_SCALE 0.35355339059327373f
#define CISTRIDE 424                 // float stride between ci slices in smem (==8 mod 32)

// ---------------- scratch ----------------
__device__ float g_local[NB*NC*HW128*HW128];
__device__ float g_qkv [NB*3*NC*HW128*HW128];
__device__ float g_o   [NB*NC*HW128*HW128];
__device__ float g_sum [NB*NC*HW128*HW128];
__device__ float g_dw  [NB*NC*HW128*HW128];
__device__ float g_xc  [NIMG*NS*NS];
__device__ float g_xc2 [NIMG*NS*NS];
__device__ float g_cr1 [NIMG*NS*NS];
__device__ float g_ci1 [NIMG*NS*NS];
__device__ float g_cr2 [NIMG*NS*NS];
__device__ float g_ci2 [NIMG*NS*NS];
__device__ float g_p   [NIMG*NS*NS];
__device__ float g_q   [NIMG*125*125];
__device__ float g_r   [NIMG*62*62];
__device__ float g_s   [NIMG*31*31];
__device__ float g_t   [NB*NC*HW128*HW128];
__device__ float g_u   [NB*NC*HW128*HW128];
__device__ float g_v   [NB*NC*HW128*HW128];
__device__ float g_Cm  [NS*NS];
__device__ float g_Sm  [NS*NS];
__device__ float g_wl  [64*64*9];
__device__ float g_bl  [64];
__device__ float g_wgab[64*64*9];
__device__ float g_bgab[64];
// tf32-transposed weights (hi + lo): l(36864) gab(36864) post(36864) gc1(36864) gc2(4096) qkv(12288) pw(4096)
__device__ float g_wT  [167936];
__device__ float g_wTlo[167936];
#define WT_L    0
#define WT_GAB  36864
#define WT_POST 73728
#define WT_GC1  110592
#define WT_GC2  147456
#define WT_QKV  151552
#define WT_PW   163840

__device__ __forceinline__ float tf32_hi(float v)
{
    uint32_t t;
    asm("cvt.rna.tf32.f32 %0, %1;" : "=r"(t) : "f"(v));
    return __uint_as_float(t);
}

// ---------------- weight-prep kernels ----------------
__global__ void prep_l_k(const float* __restrict__ w1, const float* __restrict__ gg1,
                         const float* __restrict__ bb1, const float* __restrict__ w2,
                         const float* __restrict__ gg2, const float* __restrict__ bb2)
{
    int idx = blockIdx.x * blockDim.x + threadIdx.x;
    if (idx < 64*64*9) {
        int co = idx / (64*9);
        int rem = idx - co * (64*9);
        int ci = rem / 9, k = rem - ci * 9;
        float v = w1[idx] * (gg1[co] * BN_SC);
        if (k == 4) v += w2[co*64 + ci] * (gg2[co] * BN_SC);
        g_wl[idx] = v;
    }
    if (idx < 64) g_bl[idx] = bb1[idx] + bb2[idx];
}

__global__ void prep_gab_k(const float* __restrict__ fc, const float* __restrict__ fs,
                           const float* __restrict__ bc, const float* __restrict__ bs)
{
    int idx = blockIdx.x * blockDim.x + threadIdx.x;
    if (idx < 64*64*9) {
        int co = idx / (64*9);
        g_wgab[idx] = (co < 32) ? fc[idx] : fs[idx - 32*64*9];
    }
    if (idx < 64) g_bgab[idx] = (idx < 32) ? bc[idx] : bs[idx - 32];
}

// transpose W[Cout][64][KK] -> wT[(cc*8+g)*KK + kp][co(64)][ci8], split hi/lo tf32
__global__ void prep_wT_k(const float* __restrict__ w, float* __restrict__ dhi,
                          float* __restrict__ dlo, int Cout, int KK)
{
    int idx = blockIdx.x * blockDim.x + threadIdx.x;
    int total = Cout * 64 * KK;
    if (idx >= total) return;
    int co = idx / (64 * KK);
    int rem = idx - co * (64 * KK);
    int ci = rem / KK, kp = rem - ci * KK;
    int cc = co >> 6, col = co & 63;
    int g = ci >> 3, cil = ci & 7;
    float v = w[idx];
    float hi = tf32_hi(v);
    float lo = tf32_hi(v - hi);
    size_t o = (((size_t)cc * 8 + g) * KK + kp) * 512 + col * 8 + cil;
    dhi[o] = hi;
    dlo[o] = lo;
}

// ---------------- tensor-core implicit-GEMM conv (3xTF32) ----------------
// block = 128 threads (4 warps). one block = (out row r0, co chunk of 64, batch).
// GEMM: M=64 co x N=128 cols x K = 64ci*KK, staged in 8-ci groups.
template<int K>
__global__ void __launch_bounds__(128)
convtc(const float* __restrict__ in, const float* __restrict__ wT,
       const float* __restrict__ wTlo,
       const float* __restrict__ bias, const float* __restrict__ bng,
       const float* __restrict__ bnb, float* __restrict__ out,
       int Hin, int Win, int CoutTotal, int coOff, int pad,
       int Hout, int Wout, int act)
{
    constexpr int KK = K * K;
    constexpr int WCHUNK = KK * 512;            // floats per ci-group (one of hi/lo)
    constexpr int ICHUNK = 8 * CISTRIDE;
    extern __shared__ float smem[];
    float* sW  = smem;                          // [2][2][WCHUNK]  buf, hi/lo
    float* sIn = smem + 4 * WCHUNK;             // [2][2][ICHUNK]  buf, hi/lo

    int r0 = blockIdx.x;
    int cc = blockIdx.y;
    int b  = blockIdx.z;
    int tid = threadIdx.x;
    int warp = tid >> 5, lane = tid & 31;
    int gid = lane >> 2, tig = lane & 3;
    int m0 = warp * 16;

    const float* inb    = in + (size_t)b * 64 * Hin * Win;
    const float* wbaseH = wT   + (size_t)cc * (64 * 64 * KK);
    const float* wbaseL = wTlo + (size_t)cc * (64 * 64 * KK);

    const int JW = 130;
    auto loadGroup = [&](int g, int buf) {
        uint32_t wdst = (uint32_t)__cvta_generic_to_shared(&sW[buf * 2 * WCHUNK]);
        const float* whs = wbaseH + (size_t)g * WCHUNK;
        const float* wls = wbaseL + (size_t)g * WCHUNK;
        for (int i = tid; i < WCHUNK / 4; i += 128) {
            asm volatile("cp.async.cg.shared.global [%0], [%1], 16;"
                         :: "r"(wdst + i * 16), "l"(whs + i * 4));
            asm volatile("cp.async.cg.shared.global [%0], [%1], 16;"
                         :: "r"(wdst + (WCHUNK + i * 4) * 4), "l"(wls + i * 4));
        }
        uint32_t idst = (uint32_t)__cvta_generic_to_shared(&sIn[buf * 2 * ICHUNK]);
        int ci0 = g * 8;
        int total = 8 * K * JW;
        for (int t = tid; t < total; t += 128) {
            int ci = t / (K * JW);
            int rem = t - ci * (K * JW);
            int ky = rem / JW;
            int j = rem - ky * JW;
            int gy = r0 + ky - pad;
            int gx = j - pad;
            int valid = (gy >= 0 && gy < Hin && gx >= 0 && gx < Win) ? 4 : 0;
            const float* src = inb + (size_t)(ci0 + ci) * Hin * Win;
            const float* gp = valid ? (src + (size_t)gy * Win + gx) : src;
            uint32_t d = idst + (uint32_t)((ci * CISTRIDE + ky * 132 + j) * 4);
            asm volatile("cp.async.ca.shared.global [%0], [%1], 4, %2;"
                         :: "r"(d), "l"(gp), "r"(valid));
        }
        asm volatile("cp.async.commit_group;");
    };

    // split staged fp32 inputs into hi (in place) + lo (second region)
    auto cvtIn = [&](int buf) {
        float* ph = &sIn[buf * 2 * ICHUNK];
        float* pl = ph + ICHUNK;
        for (int i = tid * 4; i < ICHUNK; i += 512) {
            float4 v = *(float4*)(ph + i);
            float4 h, l;
            h.x = tf32_hi(v.x); l.x = tf32_hi(v.x - h.x);
            h.y = tf32_hi(v.y); l.y = tf32_hi(v.y - h.y);
            h.z = tf32_hi(v.z); l.z = tf32_hi(v.z - h.z);
            h.w = tf32_hi(v.w); l.w = tf32_hi(v.w - h.w);
            *(float4*)(ph + i) = h;
            *(float4*)(pl + i) = l;
        }
    };

    float acc[16][4];
#pragma unroll
    for (int nt = 0; nt < 16; nt++)
#pragma unroll
        for (int i = 0; i < 4; i++) acc[nt][i] = 0.f;

    loadGroup(0, 0);
    for (int g = 0; g < 8; g++) {
        asm volatile("cp.async.wait_group 0;" ::: "memory");
        __syncthreads();
        cvtIn(g & 1);
        __syncthreads();
        if (g < 7) loadGroup(g + 1, (g + 1) & 1);
        const float* WH = &sW[(g & 1) * 2 * WCHUNK];
        const float* WL = WH + WCHUNK;
        const float* IH = &sIn[(g & 1) * 2 * ICHUNK];
        const float* IL = IH + ICHUNK;
#pragma unroll
        for (int kp = 0; kp < KK; kp++) {
            int ky = kp / K, kx = kp - ky * K;
            const float* wkh = WH + kp * 512;
            const float* wkl = WL + kp * 512;
            uint32_t ah0 = __float_as_uint(wkh[(m0 + gid) * 8 + tig]);
            uint32_t ah1 = __float_as_uint(wkh[(m0 + gid + 8) * 8 + tig]);
            uint32_t ah2 = __float_as_uint(wkh[(m0 + gid) * 8 + tig + 4]);
            uint32_t ah3 = __float_as_uint(wkh[(m0 + gid + 8) * 8 + tig + 4]);
            uint32_t al0 = __float_as_uint(wkl[(m0 + gid) * 8 + tig]);
            uint32_t al1 = __float_as_uint(wkl[(m0 + gid + 8) * 8 + tig]);
            uint32_t al2 = __float_as_uint(wkl[(m0 + gid) * 8 + tig + 4]);
            uint32_t al3 = __float_as_uint(wkl[(m0 + gid + 8) * 8 + tig + 4]);
            int ibo = ky * 132 + kx + gid;
            const float* ibh = IH + ibo;
            const float* ibl = IL + ibo;
#pragma unroll
            for (int nt = 0; nt < 16; nt++) {
                uint32_t bh0 = __float_as_uint(ibh[tig * CISTRIDE + nt * 8]);
                uint32_t bh1 = __float_as_uint(ibh[(tig + 4) * CISTRIDE + nt * 8]);
                uint32_t bl0 = __float_as_uint(ibl[tig * CISTRIDE + nt * 8]);
                uint32_t bl1 = __float_as_uint(ibl[(tig + 4) * CISTRIDE + nt * 8]);
                asm volatile(
                    "mma.sync.aligned.m16n8k8.row.col.f32.tf32.tf32.f32 "
                    "{%0,%1,%2,%3}, {%4,%5,%6,%7}, {%8,%9}, {%0,%1,%2,%3};"
                    : "+f"(acc[nt][0]), "+f"(acc[nt][1]), "+f"(acc[nt][2]), "+f"(acc[nt][3])
                    : "r"(ah0), "r"(ah1), "r"(ah2), "r"(ah3), "r"(bl0), "r"(bl1));
                asm volatile(
                    "mma.sync.aligned.m16n8k8.row.col.f32.tf32.tf32.f32 "
                    "{%0,%1,%2,%3}, {%4,%5,%6,%7}, {%8,%9}, {%0,%1,%2,%3};"
                    : "+f"(acc[nt][0]), "+f"(acc[nt][1]), "+f"(acc[nt][2]), "+f"(acc[nt][3])
                    : "r"(al0), "r"(al1), "r"(al2), "r"(al3), "r"(bh0), "r"(bh1));
                asm volatile(
                    "mma.sync.aligned.m16n8k8.row.col.f32.tf32.tf32.f32 "
                    "{%0,%1,%2,%3}, {%4,%5,%6,%7}, {%8,%9}, {%0,%1,%2,%3};"
                    : "+f"(acc[nt][0]), "+f"(acc[nt][1]), "+f"(acc[nt][2]), "+f"(acc[nt][3])
                    : "r"(ah0), "r"(ah1), "r"(ah2), "r"(ah3), "r"(bh0), "r"(bh1));
            }
        }
        __syncthreads();
    }

    // epilogue: rows co_g = cc*64+m0+gid and +8; cols nt*8 + 2*tig (+1)
    int coA = cc * 64 + m0 + gid;
    int coB = coA + 8;
    float biA = bias ? bias[coA] : 0.f;
    float biB = bias ? bias[coB] : 0.f;
    float scA = 1.f, shA = 0.f, scB = 1.f, shB = 0.f;
    if (bng) {
        scA = bng[coA] * BN_SC; shA = bnb[coA];
        scB = bng[coB] * BN_SC; shB = bnb[coB];
    }
    size_t rowA = ((size_t)(b * CoutTotal + coOff + coA) * Hout + r0) * Wout;
    size_t rowB = ((size_t)(b * CoutTotal + coOff + coB) * Hout + r0) * Wout;
#pragma unroll
    for (int nt = 0; nt < 16; nt++) {
        int nb = nt * 8 + 2 * tig;
        if (nb >= Wout) continue;
        float v0 = acc[nt][0] + biA, v1 = acc[nt][1] + biA;
        float v2 = acc[nt][2] + biB, v3 = acc[nt][3] + biB;
        if (bng) {
            v0 = v0 * scA + shA; v1 = v1 * scA + shA;
            v2 = v2 * scB + shB; v3 = v3 * scB + shB;
        }
        if (act == 1) {
            v0 = fmaxf(v0, 0.f); v1 = fmaxf(v1, 0.f);
            v2 = fmaxf(v2, 0.f); v3 = fmaxf(v3, 0.f);
        } else if (act == 2) {
            v0 = fminf(fmaxf(v0, 0.f), 6.f); v1 = fminf(fmaxf(v1, 0.f), 6.f);
            v2 = fminf(fmaxf(v2, 0.f), 6.f); v3 = fminf(fmaxf(v3, 0.f), 6.f);
        }
        *(float2*)&out[rowA + nb] = make_float2(v0, v1);
        *(float2*)&out[rowB + nb] = make_float2(v2, v3);
    }
}

// ---------------- fp32 direct conv (kept for stride-2) ----------------
template<int K, int STRIDE>
__global__ void __launch_bounds__(256)
conv_t(const float* __restrict__ in, const float* __restrict__ w,
       const float* __restrict__ bias, const float* __restrict__ bng,
       const float* __restrict__ bnb, float* __restrict__ out,
       int Hin, int Win, int Cout, int CoutTotal, int coOff,
       int pad, int Hout, int Wout, int act, int accum)
{
    constexpr int KK = K * K;
    constexpr int TS = 32;
    constexpr int SPAN = (TS - 1) * STRIDE + K;
    constexpr int R = STRIDE + K;
    __shared__ __align__(16) float sW[64 * KK * 8];
    __shared__ float sIn1[SPAN * SPAN];

    int tileW = (Wout + TS - 1) / TS;
    int tX = blockIdx.x % tileW, tY = blockIdx.x / tileW;
    int ow0 = tX * TS, oh0 = tY * TS;
    int co0 = blockIdx.y << 3;
    int b   = blockIdx.z;
    int tid = threadIdx.x;
    int ty = tid >> 4, tx = tid & 15;

    for (int t = tid; t < 64 * KK * 8; t += 256) {
        int row = t >> 3, co = t & 7;
        int ci = row / KK, kp = row - ci * KK;
        sW[t] = (co0 + co < Cout) ? w[(size_t)(co0 + co) * (64 * KK) + ci * KK + kp] : 0.f;
    }

    int ih0 = oh0 * STRIDE - pad, iw0 = ow0 * STRIDE - pad;
    float acc[8][2][2];
#pragma unroll
    for (int co = 0; co < 8; co++)
#pragma unroll
        for (int oy = 0; oy < 2; oy++)
#pragma unroll
            for (int ox = 0; ox < 2; ox++) acc[co][oy][ox] = 0.f;

    const float* inb = in + (size_t)b * 64 * Hin * Win;
    int base = (ty * 2 * STRIDE) * SPAN + tx * 2 * STRIDE;

    for (int ci = 0; ci < 64; ci++) {
        __syncthreads();
        const float* ip = inb + (size_t)ci * Hin * Win;
        for (int t = tid; t < SPAN * SPAN; t += 256) {
            int iy = t / SPAN, ix = t - iy * SPAN;
            int gy = ih0 + iy, gx = iw0 + ix;
            sIn1[t] = (gy >= 0 && gy < Hin && gx >= 0 && gx < Win)
                          ? __ldg(&ip[(size_t)gy * Win + gx]) : 0.f;
        }
        __syncthreads();
        float xin[R][R];
#pragma unroll
        for (int r = 0; r < R; r++)
#pragma unroll
            for (int c = 0; c < R; c++) xin[r][c] = sIn1[base + r * SPAN + c];
        const float4* wq = reinterpret_cast<const float4*>(&sW[ci * KK * 8]);
#pragma unroll
        for (int kp = 0; kp < KK; kp++) {
            float4 wa = wq[kp * 2], wb = wq[kp * 2 + 1];
            float wv[8] = {wa.x, wa.y, wa.z, wa.w, wb.x, wb.y, wb.z, wb.w};
            int ky = kp / K, kx = kp - ky * K;
#pragma unroll
            for (int oy = 0; oy < 2; oy++)
#pragma unroll
                for (int ox = 0; ox < 2; ox++) {
                    float xv = xin[oy * STRIDE + ky][ox * STRIDE + kx];
#pragma unroll
                    for (int co = 0; co < 8; co++)
                        acc[co][oy][ox] += xv * wv[co];
                }
        }
    }

#pragma unroll
    for (int co = 0; co < 8; co++) {
        int gco = co0 + co;
        if (gco >= Cout) break;
        float bi = bias ? bias[gco] : 0.f;
        float sc = 1.f, sh = 0.f;
        if (bng) { sc = bng[gco] * BN_SC; sh = bnb[gco]; }
#pragma unroll
        for (int oy = 0; oy < 2; oy++) {
            int oh = oh0 + ty * 2 + oy;
            if (oh >= Hout) continue;
#pragma unroll
            for (int ox = 0; ox < 2; ox++) {
                int ow = ow0 + tx * 2 + ox;
                if (ow >= Wout) continue;
                float v = acc[co][oy][ox] + bi;
                if (bng) v = v * sc + sh;
                if (act == 1) v = fmaxf(v, 0.f);
                else if (act == 2) v = fminf(fmaxf(v, 0.f), 6.f);
                size_t oidx = (((size_t)b * CoutTotal + coOff + gco) * Hout + oh) * Wout + ow;
                if (accum) out[oidx] += v; else out[oidx] = v;
            }
        }
    }
}

// ---------------- DFT matrices ----------------
__global__ void initdft_k()
{
    int idx = blockIdx.x * blockDim.x + threadIdx.x;
    if (idx >= NS * NS) return;
    int u = idx / NS, h = idx % NS;
    int m = (u * h) % NS;
    float xx = (2.0f * (float)m) / (float)NS;
    g_Cm[idx] = cospif(xx);
    g_Sm[idx] = sinpif(xx);
}

// ---------------- DFT GEMM stages ----------------
template<int MODE>
__global__ void __launch_bounds__(256)
cgemm_t(const float* __restrict__ Xr, const float* __restrict__ Xi,
        float* __restrict__ Cr, float* __restrict__ Ci,
        const float* __restrict__ xcIn, const float* __restrict__ gbw,
        float* __restrict__ outbuf)
{
    __shared__ __align__(16) float sAr[8][64], sAi[8][64], sBr[8][64], sBi[8][64];
    size_t off = (size_t)blockIdx.z * (NS * NS);
    int row0 = blockIdx.y * 64, col0 = blockIdx.x * 64;
    int tx = threadIdx.x, ty = threadIdx.y;
    int tid = ty * 16 + tx;
    float aR[4][4], aI[4][4];
#pragma unroll
    for (int r = 0; r < 4; r++)
#pragma unroll
        for (int c = 0; c < 4; c++) { aR[r][c] = 0.f; aI[r][c] = 0.f; }

    for (int k0 = 0; k0 < NS; k0 += 8) {
        for (int t = tid; t < 512; t += 256) {
            int kk = t >> 6, r = t & 63;
            int gk = k0 + kk;
            int gi = row0 + r;
            float ar = 0.f, ai = 0.f;
            if (gi < NS && gk < NS) {
                if constexpr (MODE == 1 || MODE == 3) {
                    ar = g_Cm[gi * NS + gk];
                    ai = (MODE == 1) ? -g_Sm[gi * NS + gk] : g_Sm[gi * NS + gk];
                } else {
                    size_t o = off + (size_t)gi * NS + gk;
                    ar = Xr[o]; ai = Xi[o];
                }
            }
            sAr[kk][r] = ar; sAi[kk][r] = ai;
            int gj = col0 + r;
            float br = 0.f, bi = 0.f;
            if (gj < NS && gk < NS) {
                if constexpr (MODE == 1) {
                    br = Xr[off + (size_t)gk * NS + gj];
                } else if constexpr (MODE == 3) {
                    size_t o = off + (size_t)gk * NS + gj;
                    br = Xr[o]; bi = Xi[o];
                } else {
                    br = g_Cm[gk * NS + gj];
                    bi = (MODE == 2) ? -g_Sm[gk * NS + gj] : g_Sm[gk * NS + gj];
                }
            }
            sBr[kk][r] = br;
            if constexpr (MODE != 1) sBi[kk][r] = bi;
        }
        __syncthreads();
#pragma unroll
        for (int kk = 0; kk < 8; kk++) {
            float4 a4r = *(const float4*)&sAr[kk][ty * 4];
            float4 a4i = *(const float4*)&sAi[kk][ty * 4];
            float4 b4r = *(const float4*)&sBr[kk][tx * 4];
            float ar[4] = {a4r.x, a4r.y, a4r.z, a4r.w};
            float ai[4] = {a4i.x, a4i.y, a4i.z, a4i.w};
            float br[4] = {b4r.x, b4r.y, b4r.z, b4r.w};
            if constexpr (MODE == 1) {
#pragma unroll
                for (int r = 0; r < 4; r++)
#pragma unroll
                    for (int c = 0; c < 4; c++) {
                        aR[r][c] += ar[r] * br[c];
                        aI[r][c] += ai[r] * br[c];
                    }
            } else {
                float4 b4i = *(const float4*)&sBi[kk][tx * 4];
                float bi[4] = {b4i.x, b4i.y, b4i.z, b4i.w};
                if constexpr (MODE == 4) {
#pragma unroll
                    for (int r = 0; r < 4; r++)
#pragma unroll
                        for (int c = 0; c < 4; c++)
                            aR[r][c] += ar[r] * br[c] - ai[r] * bi[c];
                } else {
#pragma unroll
                    for (int r = 0; r < 4; r++)
#pragma unroll
                        for (int c = 0; c < 4; c++) {
                            aR[r][c] += ar[r] * br[c] - ai[r] * bi[c];
                            aI[r][c] += ar[r] * bi[c] + ai[r] * br[c];
                        }
                }
            }
        }
        __syncthreads();
    }

    float fw0 = 0.f, fw1 = 0.f;
    if constexpr (MODE == 4) {
        float w0 = fmaxf(gbw[0], 0.f), w1 = fmaxf(gbw[1], 0.f);
        float d = w0 + w1 + 1e-8f;
        fw0 = (w0 / d) * (1.0f / (126.0f * 126.0f));
        fw1 = w1 / d;
    }
#pragma unroll
    for (int r = 0; r < 4; r++)
#pragma unroll
        for (int c = 0; c < 4; c++) {
            int gi = row0 + ty * 4 + r, gj = col0 + tx * 4 + c;
            if (gi < NS && gj < NS) {
                size_t o = off + (size_t)gi * NS + gj;
                if constexpr (MODE == 2) {
                    int su = (gi < 63) ? gi : gi - NS;
                    int sv = (gj < 63) ? gj : gj - NS;
                    float rr = aR[r][c], ii = aI[r][c];
                    float s = (su * su + sv * sv > 1600)
                                  ? sqrtf(rr * rr + ii * ii) : 0.f;
                    Cr[o] = rr * s; Ci[o] = ii * s;
                } else if constexpr (MODE == 4) {
                    outbuf[o] = fw0 * fabsf(aR[r][c]) + fw1 * xcIn[o];
                } else {
                    Cr[o] = aR[r][c]; Ci[o] = aI[r][c];
                }
            }
        }
}

// ---------------- maxpools ----------------
__global__ void mp21_k(const float* __restrict__ in, float* __restrict__ out)
{
    int idx = blockIdx.x * blockDim.x + threadIdx.x;
    int n = NIMG * 125 * 125;
    if (idx >= n) return;
    int w = idx % 125, h = (idx / 125) % 125, ch = idx / (125 * 125);
    const float* p = in + (size_t)ch * NS * NS + (size_t)h * NS + w;
    out[idx] = fmaxf(fmaxf(p[0], p[1]), fmaxf(p[NS], p[NS + 1]));
}
__global__ void mp22_k(const float* __restrict__ in, float* __restrict__ out)
{
    int idx = blockIdx.x * blockDim.x + threadIdx.x;
    int n = NIMG * 31 * 31;
    if (idx >= n) return;
    int w = idx % 31, h = (idx / 31) % 31, ch = idx / (31 * 31);
    const float* p = in + (size_t)ch * 62 * 62 + (size_t)(2 * h) * 62 + 2 * w;
    out[idx] = fmaxf(fmaxf(p[0], p[1]), fmaxf(p[62], p[63]));
}

// ---------------- bilinear resize 31 -> 128 ----------------
__global__ void resize_k(const float* __restrict__ in, float* __restrict__ out)
{
    int idx = blockIdx.x * blockDim.x + threadIdx.x;
    int n = NIMG * HW128 * HW128;
    if (idx >= n) return;
    int x = idx & 127, y = (idx >> 7) & 127, ch = idx >> 14;
    const float sc = 31.f / 128.f;
    float sy = fminf(fmaxf((y + 0.5f) * sc - 0.5f, 0.f), 30.f);
    float sx = fminf(fmaxf((x + 0.5f) * sc - 0.5f, 0.f), 30.f);
    int y0 = (int)floorf(sy); float fy = sy - y0; int y1 = min(y0 + 1, 30);
    int x0 = (int)floorf(sx); float fx = sx - x0; int x1 = min(x0 + 1, 30);
    const float* p = in + (size_t)ch * 961;
    float v = (1.f - fy) * ((1.f - fx) * p[y0 * 31 + x0] + fx * p[y0 * 31 + x1])
            + fy         * ((1.f - fx) * p[y1 * 31 + x0] + fx * p[y1 * 31 + x1]);
    out[idx] = v;
}

// ---------------- log_softmax over channels ----------------
__global__ void lsm_k(const float* __restrict__ in, float* __restrict__ out)
{
    int gid = blockIdx.x * blockDim.x + threadIdx.x;
    if (gid >= NB * HW128 * HW128) return;
    int b = gid >> 14, p = gid & 16383;
    size_t base = (size_t)b * NC * 16384 + p;
    float mx = -1e30f;
    for (int c = 0; c < NC; c++) mx = fmaxf(mx, in[base + (size_t)c * 16384]);
    float s = 0.f;
    for (int c = 0; c < NC; c++) s += expf(in[base + (size_t)c * 16384] - mx);
    float l = logf(s);
    for (int c = 0; c < NC; c++) {
        size_t o = base + (size_t)c * 16384;
        out[o] = in[o] - mx - l;
    }
}

// ---------------- windowed attention ----------------
__global__ void attn_k(const float* __restrict__ qkv, const float* __restrict__ rpb,
                       const int* __restrict__ relidx, float* __restrict__ o)
{
    __shared__ float sk[64][8];
    __shared__ float sv[64][8];
    int win = blockIdx.x;
    int gh = win >> 4, gw = win & 15;
    int n = blockIdx.y, b = blockIdx.z;
    int i = threadIdx.x;
    int hi = gh * 8 + (i >> 3), wi = gw * 8 + (i & 7);
    float q[8];
#pragma unroll
    for (int d = 0; d < 8; d++) {
        int cq = n * 8 + d;
        size_t sp = (size_t)hi * 128 + wi;
        q[d]      = qkv[(((size_t)b * 192 + cq)       * 16384) + sp];
        sk[i][d]  = qkv[(((size_t)b * 192 + 64 + cq)  * 16384) + sp];
        sv[i][d]  = qkv[(((size_t)b * 192 + 128 + cq) * 16384) + sp];
    }
    __syncthreads();
    float logits[64];
    float mx = -1e30f;
#pragma unroll
    for (int j = 0; j < 64; j++) {
        float dot = 0.f;
#pragma unroll
        for (int d = 0; d < 8; d++) dot += q[d] * sk[j][d];
        float l = dot * ATTN_SCALE + rpb[relidx[i * 64 + j] * 8 + n];
        logits[j] = l;
        mx = fmaxf(mx, l);
    }
    float se = 0.f;
#pragma unroll
    for (int j = 0; j < 64; j++) { float e = expf(logits[j] - mx); logits[j] = e; se += e; }
    float inv = 1.f / se;
    float od[8];
#pragma unroll
    for (int d = 0; d < 8; d++) od[d] = 0.f;
#pragma unroll
    for (int j = 0; j < 64; j++) {
#pragma unroll
        for (int d = 0; d < 8; d++) od[d] += logits[j] * sv[j][d];
    }
#pragma unroll
    for (int d = 0; d < 8; d++)
        o[(((size_t)b * 64 + n * 8 + d) * 128 + hi) * 128 + wi] = od[d] * inv;
}

// ---------------- directional pools + add local ----------------
__global__ void poolsum_k(const float* __restrict__ o, const float* __restrict__ loc,
                          float* __restrict__ out)
{
    int idx = blockIdx.x * blockDim.x + threadIdx.x;
    int n = NB * NC * HW128 * HW128;
    if (idx >= n) return;
    int w = idx & 127, h = (idx >> 7) & 127;
    size_t chbase = (size_t)(idx >> 14) * 16384;
    float sx = 0.f;
#pragma unroll
    for (int t = -3; t <= 4; t++) {
        int r = h + t;
        if (r >= 0 && r <= 128) { if (r == 128) r = 126; sx += o[chbase + (size_t)r * 128 + w]; }
    }
    float sy = 0.f;
#pragma unroll
    for (int t = -3; t <= 4; t++) {
        int c = w + t;
        if (c >= 0 && c <= 128) { if (c == 128) c = 126; sy += o[chbase + (size_t)h * 128 + c]; }
    }
    out[idx] = (sx + sy) * 0.125f + loc[idx];
}

// ---------------- depthwise 8x8 conv + BN ----------------
__global__ void dwconv_k(const float* __restrict__ in, const float* __restrict__ w,
                         const float* __restrict__ bng, const float* __restrict__ bnb,
                         float* __restrict__ out)
{
    __shared__ float sIn[23 * 23];
    __shared__ float sWt[64];
    int tile = blockIdx.x;
    int tX = tile & 7, tY = tile >> 3;
    int c = blockIdx.y, b = blockIdx.z;
    int tid = threadIdx.y * 16 + threadIdx.x;
    if (tid < 64) sWt[tid] = w[c * 64 + tid];
    int h0 = tY * 16 - 3, w0 = tX * 16 - 3;
    const float* ip = in + (size_t)(b * 64 + c) * 16384;
    for (int t = tid; t < 23 * 23; t += 256) {
        int iy = t / 23, ix = t - iy * 23;
        int gy = h0 + iy, gx = w0 + ix;
        sIn[t] = (gy >= 0 && gy < 128 && gx >= 0 && gx < 128) ? ip[(size_t)gy * 128 + gx] : 0.f;
    }
    __syncthreads();
    float acc = 0.f;
#pragma unroll
    for (int i = 0; i < 8; i++)
#pragma unroll
        for (int j = 0; j < 8; j++)
            acc += sIn[(threadIdx.y + i) * 23 + threadIdx.x + j] * sWt[i * 8 + j];
    float v = acc * (bng[c] * BN_SC) + bnb[c];
    out[((size_t)(b * 64 + c) * 128 + tY * 16 + threadIdx.y) * 128 + tX * 16 + threadIdx.x] = v;
}

// ---------------- host ----------------
extern "C" void kernel_launch(void* const* d_in, const int* in_sizes, int n_in,
                              void* d_out, int out_size)
{
    const float* x       = (const float*)d_in[0];
    const float* w_qkv   = (const float*)d_in[1];
    const float* w_l1    = (const float*)d_in[2];
    const float* gl1     = (const float*)d_in[3];
    const float* bl1     = (const float*)d_in[4];
    const float* w_l2    = (const float*)d_in[5];
    const float* gl2     = (const float*)d_in[6];
    const float* bl2     = (const float*)d_in[7];
    const float* f_cos   = (const float*)d_in[8];
    const float* f_sin   = (const float*)d_in[9];
    const float* gb_b1   = (const float*)d_in[10];
    const float* gb_b2   = (const float*)d_in[11];
    const float* gb_w    = (const float*)d_in[12];
    const float* w_post  = (const float*)d_in[13];
    const float* g_postp = (const float*)d_in[14];
    const float* b_postp = (const float*)d_in[15];
    const float* w_gc    = (const float*)d_in[16];
    const float* b_gc    = (const float*)d_in[17];
    const float* w_gc1   = (const float*)d_in[18];
    const float* b_gc1   = (const float*)d_in[19];
    const float* w_gc2   = (const float*)d_in[20];
    const float* b_gc2   = (const float*)d_in[21];
    const float* rpb     = (const float*)d_in[22];
    const float* w_dw    = (const float*)d_in[23];
    const float* g_proj  = (const float*)d_in[24];
    const float* b_proj  = (const float*)d_in[25];
    const float* w_pw    = (const float*)d_in[26];
    const int*   relidx  = (const int*)  d_in[27];
    float* out = (float*)d_out;

    float *loc, *qkv, *obuf, *sum, *dw, *xc, *xc2, *cr1, *ci1, *cr2, *ci2;
    float *pb, *qb, *rb, *sb, *tb, *ub, *vb, *wl, *bl, *wgab, *bgab, *wT, *wTlo;
    cudaGetSymbolAddress((void**)&loc,  g_local);
    cudaGetSymbolAddress((void**)&qkv,  g_qkv);
    cudaGetSymbolAddress((void**)&obuf, g_o);
    cudaGetSymbolAddress((void**)&sum,  g_sum);
    cudaGetSymbolAddress((void**)&dw,   g_dw);
    cudaGetSymbolAddress((void**)&xc,   g_xc);
    cudaGetSymbolAddress((void**)&xc2,  g_xc2);
    cudaGetSymbolAddress((void**)&cr1,  g_cr1);
    cudaGetSymbolAddress((void**)&ci1,  g_ci1);
    cudaGetSymbolAddress((void**)&cr2,  g_cr2);
    cudaGetSymbolAddress((void**)&ci2,  g_ci2);
    cudaGetSymbolAddress((void**)&pb,   g_p);
    cudaGetSymbolAddress((void**)&qb,   g_q);
    cudaGetSymbolAddress((void**)&rb,   g_r);
    cudaGetSymbolAddress((void**)&sb,   g_s);
    cudaGetSymbolAddress((void**)&tb,   g_t);
    cudaGetSymbolAddress((void**)&ub,   g_u);
    cudaGetSymbolAddress((void**)&vb,   g_v);
    cudaGetSymbolAddress((void**)&wl,   g_wl);
    cudaGetSymbolAddress((void**)&bl,   g_bl);
    cudaGetSymbolAddress((void**)&wgab, g_wgab);
    cudaGetSymbolAddress((void**)&bgab, g_bgab);
    cudaGetSymbolAddress((void**)&wT,   g_wT);
    cudaGetSymbolAddress((void**)&wTlo, g_wTlo);

    const int T = 256;
    const int SM3 = (4 * 9 * 512 + 4 * 8 * CISTRIDE) * 4;   // 128000 B
    const int SM1 = (4 * 1 * 512 + 4 * 8 * CISTRIDE) * 4;   // 62464 B
    cudaFuncSetAttribute(convtc<3>, cudaFuncAttributeMaxDynamicSharedMemorySize, SM3);
    cudaFuncSetAttribute(convtc<1>, cudaFuncAttributeMaxDynamicSharedMemorySize, SM1);

    // weight prep + DFT tables
    prep_l_k<<<(64*64*9 + T - 1)/T, T>>>(w_l1, gl1, bl1, w_l2, gl2, bl2);
    prep_gab_k<<<(64*64*9 + T - 1)/T, T>>>(f_cos, f_sin, gb_b1, gb_b2);
    prep_wT_k<<<(64*64*9 + T - 1)/T, T>>>(wl,     wT + WT_L,    wTlo + WT_L,    64, 9);
    prep_wT_k<<<(64*64*9 + T - 1)/T, T>>>(wgab,   wT + WT_GAB,  wTlo + WT_GAB,  64, 9);
    prep_wT_k<<<(64*64*9 + T - 1)/T, T>>>(w_post, wT + WT_POST, wTlo + WT_POST, 64, 9);
    prep_wT_k<<<(64*64*9 + T - 1)/T, T>>>(w_gc1,  wT + WT_GC1,  wTlo + WT_GC1,  64, 9);
    prep_wT_k<<<(64*64   + T - 1)/T, T>>>(w_gc2,  wT + WT_GC2,  wTlo + WT_GC2,  64, 1);
    prep_wT_k<<<(192*64  + T - 1)/T, T>>>(w_qkv,  wT + WT_QKV,  wTlo + WT_QKV, 192, 1);
    prep_wT_k<<<(64*64   + T - 1)/T, T>>>(w_pw,   wT + WT_PW,   wTlo + WT_PW,   64, 1);
    initdft_k<<<(NS*NS + T - 1)/T, T>>>();

    // local pre (merged l1+l2)
    convtc<3><<<dim3(128,1,NB), 128, SM3>>>(x, wT + WT_L, wTlo + WT_L, bl, nullptr, nullptr,
                                            loc, 128,128, 64,0, 1, 128,128, 0);
    // merged gabor conv (valid, 128->126)
    convtc<3><<<dim3(126,1,NB), 128, SM3>>>(loc, wT + WT_GAB, wTlo + WT_GAB, bgab, nullptr,
                                            nullptr, xc, 128,128, 64,0, 0, 126,126, 0);
    // DFT high-pass
    dim3 gg(2, 2, NIMG), bbk(16, 16);
    cgemm_t<1><<<gg, bbk>>>(xc,  nullptr, cr1, ci1, nullptr, nullptr, nullptr);
    cgemm_t<2><<<gg, bbk>>>(cr1, ci1,     cr2, ci2, nullptr, nullptr, nullptr);
    cgemm_t<3><<<gg, bbk>>>(cr2, ci2,     cr1, ci1, nullptr, nullptr, nullptr);
    cgemm_t<4><<<gg, bbk>>>(cr1, ci1,     nullptr, nullptr, xc, gb_w, xc2);
    // post conv + bn + relu6
    convtc<3><<<dim3(126,1,NB), 128, SM3>>>(xc2, wT + WT_POST, wTlo + WT_POST, nullptr,
                                            g_postp, b_postp, pb, 126,126, 64,0, 1, 126,126, 2);
    mp21_k<<<(NIMG*125*125 + T - 1)/T, T>>>(pb, qb);
    conv_t<3,2><<<dim3(4, 8, NB), T>>>(qb, w_gc, b_gc, nullptr, nullptr, rb,
                                       125,125, 64,64,0, 0, 62,62, 1,0);
    mp22_k<<<(NIMG*31*31 + T - 1)/T, T>>>(rb, sb);
    resize_k<<<(NIMG*16384 + T - 1)/T, T>>>(sb, tb);
    convtc<3><<<dim3(128,1,NB), 128, SM3>>>(tb, wT + WT_GC1, wTlo + WT_GC1, b_gc1, nullptr,
                                            nullptr, ub, 128,128, 64,0, 1, 128,128, 1);
    convtc<1><<<dim3(128,1,NB), 128, SM1>>>(ub, wT + WT_GC2, wTlo + WT_GC2, b_gc2, nullptr,
                                            nullptr, vb, 128,128, 64,0, 0, 128,128, 0);
    lsm_k<<<(NB*16384 + T - 1)/T, T>>>(vb, loc);
    // global branch
    convtc<1><<<dim3(128,3,NB), 128, SM1>>>(x, wT + WT_QKV, wTlo + WT_QKV, nullptr, nullptr,
                                            nullptr, qkv, 128,128, 192,0, 0, 128,128, 0);
    attn_k<<<dim3(256, NH_, NB), 64>>>(qkv, rpb, relidx, obuf);
    poolsum_k<<<(NB*NC*16384 + T - 1)/T, T>>>(obuf, loc, sum);
    dwconv_k<<<dim3(64, 64, NB), dim3(16,16)>>>(sum, w_dw, g_proj, b_proj, dw);
    convtc<1><<<dim3(128,1,NB), 128, SM1>>>(dw, wT + WT_PW, wTlo + WT_PW, nullptr, nullptr,
                                            nullptr, out, 128,128, 64,0, 0, 128,128, 0);
    (void)in_sizes; (void)n_in; (void)out_size;
}

// round 9
// speedup vs baseline: 1.8371x; 1.8371x over previous
#include <cuda_runtime.h>
#include <cuda_bf16.h>
#include <math.h>
#include <cstddef>
#include <cstdint>

// ---------------- constants ----------------
#define BN_SC 0.9999950000374997f   // 1/sqrt(1+1e-5) as float
#define NB 8
#define NC 64
#define NH_ 8
#define HW128 128
#define NS 126
#define NIMG (NB*NC)                 // 512
#define ATTN_SCALE 0.35355339059327373f

// ---------------- scratch ----------------
__device__ float g_local[NB*NC*HW128*HW128];
__device__ float g_qkv [NB*3*NC*HW128*HW128];
__device__ float g_o   [NB*NC*HW128*HW128];
__device__ float g_sum [NB*NC*HW128*HW128];
__device__ float g_dw  [NB*NC*HW128*HW128];
__device__ float g_xc  [NIMG*NS*NS];
__device__ float g_xc2 [NIMG*NS*NS];
__device__ float g_cr1 [NIMG*NS*NS];
__device__ float g_ci1 [NIMG*NS*NS];
__device__ float g_cr2 [NIMG*NS*NS];
__device__ float g_ci2 [NIMG*NS*NS];
__device__ float g_p   [NIMG*NS*NS];
__device__ float g_q   [NIMG*125*125];
__device__ float g_r   [NIMG*62*62];
__device__ float g_s   [NIMG*31*31];
__device__ float g_t   [NB*NC*HW128*HW128];
__device__ float g_u   [NB*NC*HW128*HW128];
__device__ float g_v   [NB*NC*HW128*HW128];
__device__ float g_Cm  [NS*NS];
__device__ float g_Sm  [NS*NS];
__device__ float g_wl  [64*64*9];
__device__ float g_bl  [64];
__device__ float g_wgab[64*64*9];
__device__ float g_bgab[64];
// packed bf16x2 duplicated weights (hi plane + lo plane)
// l(36864) gab(36864) post(36864) gc1(36864) gc2(4096) qkv(12288) pw(4096)
__device__ uint32_t g_wPH[167936];
__device__ uint32_t g_wPL[167936];
#define WT_L    0
#define WT_GAB  36864
#define WT_POST 73728
#define WT_GC1  110592
#define WT_GC2  147456
#define WT_QKV  151552
#define WT_PW   163840

__device__ __forceinline__ uint32_t bf_dup(float v)
{
    __nv_bfloat16 h = __float2bfloat16(v);
    uint32_t u = (uint32_t)__bfloat16_as_ushort(h);
    return u | (u << 16);
}

// ---------------- weight-prep kernels ----------------
__global__ void prep_l_k(const float* __restrict__ w1, const float* __restrict__ gg1,
                         const float* __restrict__ bb1, const float* __restrict__ w2,
                         const float* __restrict__ gg2, const float* __restrict__ bb2)
{
    int idx = blockIdx.x * blockDim.x + threadIdx.x;
    if (idx < 64*64*9) {
        int co = idx / (64*9);
        int rem = idx - co * (64*9);
        int ci = rem / 9, k = rem - ci * 9;
        float v = w1[idx] * (gg1[co] * BN_SC);
        if (k == 4) v += w2[co*64 + ci] * (gg2[co] * BN_SC);
        g_wl[idx] = v;
    }
    if (idx < 64) g_bl[idx] = bb1[idx] + bb2[idx];
}

__global__ void prep_gab_k(const float* __restrict__ fc, const float* __restrict__ fs,
                           const float* __restrict__ bc, const float* __restrict__ bs)
{
    int idx = blockIdx.x * blockDim.x + threadIdx.x;
    if (idx < 64*64*9) {
        int co = idx / (64*9);
        g_wgab[idx] = (co < 32) ? fc[idx] : fs[idx - 32*64*9];
    }
    if (idx < 64) g_bgab[idx] = (idx < 32) ? bc[idx] : bs[idx - 32];
}

// W[Cout][64][KK] -> planes [(cc*8+g)*KK + kp][co64][ci8], bf16x2-duplicated hi/lo
__global__ void prep_wP_k(const float* __restrict__ w, uint32_t* __restrict__ dh,
                          uint32_t* __restrict__ dl, int Cout, int KK)
{
    int idx = blockIdx.x * blockDim.x + threadIdx.x;
    int total = Cout * 64 * KK;
    if (idx >= total) return;
    int co = idx / (64 * KK);
    int rem = idx - co * (64 * KK);
    int ci = rem / KK, kp = rem - ci * KK;
    int cc = co >> 6, col = co & 63;
    int g = ci >> 3, cil = ci & 7;
    float v = w[idx];
    __nv_bfloat16 h = __float2bfloat16(v);
    float lo = v - __bfloat162float(h);
    size_t o = (((size_t)cc * 8 + g) * KK + kp) * 512 + col * 8 + cil;
    dh[o] = bf_dup(v);
    dl[o] = bf_dup(lo);
}

// ---------------- tensor-core implicit-GEMM conv (split-bf16, exact dup-pair) ----
// 256 threads = 8 warps: wm (4) covers M=64 co, wn (2) covers N halves of 128 cols.
// one block = (out row r0, co chunk of 64, batch). K staged in 8-ci groups.
template<int K>
__global__ void __launch_bounds__(256)
conv_bf(const float* __restrict__ in, const uint32_t* __restrict__ wH,
        const uint32_t* __restrict__ wL,
        const float* __restrict__ bias, const float* __restrict__ bng,
        const float* __restrict__ bnb, float* __restrict__ out,
        int Hin, int Win, int CoutTotal, int coOff, int pad,
        int Hout, int Wout, int act)
{
    constexpr int KK = K * K;
    constexpr int RW = (K == 3) ? 132 : 136;    // word row width inside a ci slice
    constexpr int PSTR = (K == 3) ? 424 : 136;  // ci-slice stride (==8 mod 32)
    constexpr int ICH = 8 * PSTR;               // words (= floats) per group
    constexpr int WCH = KK * 512;               // weight words per plane per group
    constexpr int JW = (K == 3) ? 130 : 128;

    extern __shared__ uint32_t smemU[];
    uint32_t* sW  = smemU;                       // [2 buf][2 plane][WCH]
    float*    sSt = (float*)(smemU + 4 * WCH);   // [2 buf][ICH] staged fp32
    uint32_t* sPk = smemU + 4 * WCH + 2 * ICH;   // [ICH] packed bf16x2

    int r0 = blockIdx.x;
    int cc = blockIdx.y;
    int b  = blockIdx.z;
    int tid = threadIdx.x;
    int warp = tid >> 5, lane = tid & 31;
    int wm = warp & 3, wn = warp >> 2;
    int gid = lane >> 2, tig = lane & 3;
    int m0 = wm * 16, n0 = wn * 64;

    const float* inb = in + (size_t)b * 64 * Hin * Win;
    const uint32_t* wHb = wH + (size_t)cc * (64 * 64 * KK);
    const uint32_t* wLb = wL + (size_t)cc * (64 * 64 * KK);

    auto loadGroup = [&](int g, int buf) {
        uint32_t wdst = (uint32_t)__cvta_generic_to_shared(&sW[buf * 2 * WCH]);
        const uint32_t* whs = wHb + (size_t)g * WCH;
        const uint32_t* wls = wLb + (size_t)g * WCH;
        for (int i = tid; i < WCH / 4; i += 256) {
            asm volatile("cp.async.cg.shared.global [%0], [%1], 16;"
                         :: "r"(wdst + i * 16), "l"(whs + i * 4));
            asm volatile("cp.async.cg.shared.global [%0], [%1], 16;"
                         :: "r"(wdst + (WCH + i * 4) * 4), "l"(wls + i * 4));
        }
        uint32_t idst = (uint32_t)__cvta_generic_to_shared(&sSt[buf * ICH]);
        int ci0 = g * 8;
        int total = 8 * K * JW;
        for (int t = tid; t < total; t += 256) {
            int ci = t / (K * JW);
            int rem = t - ci * (K * JW);
            int ky = rem / JW;
            int j = rem - ky * JW;
            int gy = r0 + ky - pad;
            int gx = j - pad;
            int valid = (gy >= 0 && gy < Hin && gx >= 0 && gx < Win) ? 4 : 0;
            const float* src = inb + (size_t)(ci0 + ci) * Hin * Win;
            const float* gp = valid ? (src + (size_t)gy * Win + gx) : src;
            uint32_t d = idst + (uint32_t)((ci * PSTR + ky * RW + j) * 4);
            asm volatile("cp.async.ca.shared.global [%0], [%1], 4, %2;"
                         :: "r"(d), "l"(gp), "r"(valid));
        }
        asm volatile("cp.async.commit_group;");
    };

    float acc[8][4];
#pragma unroll
    for (int nt = 0; nt < 8; nt++)
#pragma unroll
        for (int i = 0; i < 4; i++) acc[nt][i] = 0.f;

    loadGroup(0, 0);
    for (int g = 0; g < 8; g++) {
        asm volatile("cp.async.wait_group 0;" ::: "memory");
        __syncthreads();
        // split-convert staged fp32 -> packed (hi,lo) bf16x2 words
        {
            const float* ps = &sSt[(g & 1) * ICH];
            for (int i = tid; i < ICH; i += 256) {
                float v = ps[i];
                __nv_bfloat16 h = __float2bfloat16(v);
                float lo = v - __bfloat162float(h);
                __nv_bfloat16 l = __float2bfloat16(lo);
                sPk[i] = (uint32_t)__bfloat16_as_ushort(h)
                       | ((uint32_t)__bfloat16_as_ushort(l) << 16);
            }
        }
        __syncthreads();
        if (g < 7) loadGroup(g + 1, (g + 1) & 1);
        const uint32_t* WHp = &sW[(g & 1) * 2 * WCH];
        const uint32_t* WLp = WHp + WCH;
#pragma unroll
        for (int kp = 0; kp < KK; kp++) {
            int ky = kp / K, kx = kp - ky * K;
            const uint32_t* wkh = WHp + kp * 512;
            const uint32_t* wkl = WLp + kp * 512;
            uint32_t ah0 = wkh[(m0 + gid) * 8 + tig];
            uint32_t ah1 = wkh[(m0 + gid + 8) * 8 + tig];
            uint32_t ah2 = wkh[(m0 + gid) * 8 + tig + 4];
            uint32_t ah3 = wkh[(m0 + gid + 8) * 8 + tig + 4];
            uint32_t al0 = wkl[(m0 + gid) * 8 + tig];
            uint32_t al1 = wkl[(m0 + gid + 8) * 8 + tig];
            uint32_t al2 = wkl[(m0 + gid) * 8 + tig + 4];
            uint32_t al3 = wkl[(m0 + gid + 8) * 8 + tig + 4];
            const uint32_t* pb0 = sPk + tig * PSTR + ky * RW + kx + n0 + gid;
            const uint32_t* pb1 = sPk + (tig + 4) * PSTR + ky * RW + kx + n0 + gid;
#pragma unroll
            for (int nt = 0; nt < 8; nt++) {
                uint32_t b0 = pb0[nt * 8];
                uint32_t b1 = pb1[nt * 8];
                asm volatile(
                    "mma.sync.aligned.m16n8k16.row.col.f32.bf16.bf16.f32 "
                    "{%0,%1,%2,%3}, {%4,%5,%6,%7}, {%8,%9}, {%0,%1,%2,%3};"
                    : "+f"(acc[nt][0]), "+f"(acc[nt][1]), "+f"(acc[nt][2]), "+f"(acc[nt][3])
                    : "r"(ah0), "r"(ah1), "r"(ah2), "r"(ah3), "r"(b0), "r"(b1));
                asm volatile(
                    "mma.sync.aligned.m16n8k16.row.col.f32.bf16.bf16.f32 "
                    "{%0,%1,%2,%3}, {%4,%5,%6,%7}, {%8,%9}, {%0,%1,%2,%3};"
                    : "+f"(acc[nt][0]), "+f"(acc[nt][1]), "+f"(acc[nt][2]), "+f"(acc[nt][3])
                    : "r"(al0), "r"(al1), "r"(al2), "r"(al3), "r"(b0), "r"(b1));
            }
        }
        __syncthreads();
    }

    // epilogue: rows coA = cc*64+m0+gid, coB = +8; cols n0 + nt*8 + 2*tig (+1)
    int coA = cc * 64 + m0 + gid;
    int coB = coA + 8;
    float biA = bias ? bias[coA] : 0.f;
    float biB = bias ? bias[coB] : 0.f;
    float scA = 1.f, shA = 0.f, scB = 1.f, shB = 0.f;
    if (bng) {
        scA = bng[coA] * BN_SC; shA = bnb[coA];
        scB = bng[coB] * BN_SC; shB = bnb[coB];
    }
    size_t rowA = ((size_t)(b * CoutTotal + coOff + coA) * Hout + r0) * Wout;
    size_t rowB = ((size_t)(b * CoutTotal + coOff + coB) * Hout + r0) * Wout;
#pragma unroll
    for (int nt = 0; nt < 8; nt++) {
        int nb = n0 + nt * 8 + 2 * tig;
        if (nb >= Wout) continue;
        float v0 = acc[nt][0] + biA, v1 = acc[nt][1] + biA;
        float v2 = acc[nt][2] + biB, v3 = acc[nt][3] + biB;
        if (bng) {
            v0 = v0 * scA + shA; v1 = v1 * scA + shA;
            v2 = v2 * scB + shB; v3 = v3 * scB + shB;
        }
        if (act == 1) {
            v0 = fmaxf(v0, 0.f); v1 = fmaxf(v1, 0.f);
            v2 = fmaxf(v2, 0.f); v3 = fmaxf(v3, 0.f);
        } else if (act == 2) {
            v0 = fminf(fmaxf(v0, 0.f), 6.f); v1 = fminf(fmaxf(v1, 0.f), 6.f);
            v2 = fminf(fmaxf(v2, 0.f), 6.f); v3 = fminf(fmaxf(v3, 0.f), 6.f);
        }
        *(float2*)&out[rowA + nb] = make_float2(v0, v1);
        *(float2*)&out[rowB + nb] = make_float2(v2, v3);
    }
}

// ---------------- fp32 direct conv (kept for stride-2) ----------------
template<int K, int STRIDE>
__global__ void __launch_bounds__(256)
conv_t(const float* __restrict__ in, const float* __restrict__ w,
       const float* __restrict__ bias, const float* __restrict__ bng,
       const float* __restrict__ bnb, float* __restrict__ out,
       int Hin, int Win, int Cout, int CoutTotal, int coOff,
       int pad, int Hout, int Wout, int act, int accum)
{
    constexpr int KK = K * K;
    constexpr int TS = 32;
    constexpr int SPAN = (TS - 1) * STRIDE + K;
    constexpr int R = STRIDE + K;
    __shared__ __align__(16) float sW[64 * KK * 8];
    __shared__ float sIn1[SPAN * SPAN];

    int tileW = (Wout + TS - 1) / TS;
    int tX = blockIdx.x % tileW, tY = blockIdx.x / tileW;
    int ow0 = tX * TS, oh0 = tY * TS;
    int co0 = blockIdx.y << 3;
    int b   = blockIdx.z;
    int tid = threadIdx.x;
    int ty = tid >> 4, tx = tid & 15;

    for (int t = tid; t < 64 * KK * 8; t += 256) {
        int row = t >> 3, co = t & 7;
        int ci = row / KK, kp = row - ci * KK;
        sW[t] = (co0 + co < Cout) ? w[(size_t)(co0 + co) * (64 * KK) + ci * KK + kp] : 0.f;
    }

    int ih0 = oh0 * STRIDE - pad, iw0 = ow0 * STRIDE - pad;
    float acc[8][2][2];
#pragma unroll
    for (int co = 0; co < 8; co++)
#pragma unroll
        for (int oy = 0; oy < 2; oy++)
#pragma unroll
            for (int ox = 0; ox < 2; ox++) acc[co][oy][ox] = 0.f;

    const float* inb = in + (size_t)b * 64 * Hin * Win;
    int base = (ty * 2 * STRIDE) * SPAN + tx * 2 * STRIDE;

    for (int ci = 0; ci < 64; ci++) {
        __syncthreads();
        const float* ip = inb + (size_t)ci * Hin * Win;
        for (int t = tid; t < SPAN * SPAN; t += 256) {
            int iy = t / SPAN, ix = t - iy * SPAN;
            int gy = ih0 + iy, gx = iw0 + ix;
            sIn1[t] = (gy >= 0 && gy < Hin && gx >= 0 && gx < Win)
                          ? __ldg(&ip[(size_t)gy * Win + gx]) : 0.f;
        }
        __syncthreads();
        float xin[R][R];
#pragma unroll
        for (int r = 0; r < R; r++)
#pragma unroll
            for (int c = 0; c < R; c++) xin[r][c] = sIn1[base + r * SPAN + c];
        const float4* wq = reinterpret_cast<const float4*>(&sW[ci * KK * 8]);
#pragma unroll
        for (int kp = 0; kp < KK; kp++) {
            float4 wa = wq[kp * 2], wb = wq[kp * 2 + 1];
            float wv[8] = {wa.x, wa.y, wa.z, wa.w, wb.x, wb.y, wb.z, wb.w};
            int ky = kp / K, kx = kp - ky * K;
#pragma unroll
            for (int oy = 0; oy < 2; oy++)
#pragma unroll
                for (int ox = 0; ox < 2; ox++) {
                    float xv = xin[oy * STRIDE + ky][ox * STRIDE + kx];
#pragma unroll
                    for (int co = 0; co < 8; co++)
                        acc[co][oy][ox] += xv * wv[co];
                }
        }
    }

#pragma unroll
    for (int co = 0; co < 8; co++) {
        int gco = co0 + co;
        if (gco >= Cout) break;
        float bi = bias ? bias[gco] : 0.f;
        float sc = 1.f, sh = 0.f;
        if (bng) { sc = bng[gco] * BN_SC; sh = bnb[gco]; }
#pragma unroll
        for (int oy = 0; oy < 2; oy++) {
            int oh = oh0 + ty * 2 + oy;
            if (oh >= Hout) continue;
#pragma unroll
            for (int ox = 0; ox < 2; ox++) {
                int ow = ow0 + tx * 2 + ox;
                if (ow >= Wout) continue;
                float v = acc[co][oy][ox] + bi;
                if (bng) v = v * sc + sh;
                if (act == 1) v = fmaxf(v, 0.f);
                else if (act == 2) v = fminf(fmaxf(v, 0.f), 6.f);
                size_t oidx = (((size_t)b * CoutTotal + coOff + gco) * Hout + oh) * Wout + ow;
                if (accum) out[oidx] += v; else out[oidx] = v;
            }
        }
    }
}

// ---------------- DFT matrices ----------------
__global__ void initdft_k()
{
    int idx = blockIdx.x * blockDim.x + threadIdx.x;
    if (idx >= NS * NS) return;
    int u = idx / NS, h = idx % NS;
    int m = (u * h) % NS;
    float xx = (2.0f * (float)m) / (float)NS;
    g_Cm[idx] = cospif(xx);
    g_Sm[idx] = sinpif(xx);
}

// ---------------- DFT GEMM stages ----------------
template<int MODE>
__global__ void __launch_bounds__(256)
cgemm_t(const float* __restrict__ Xr, const float* __restrict__ Xi,
        float* __restrict__ Cr, float* __restrict__ Ci,
        const float* __restrict__ xcIn, const float* __restrict__ gbw,
        float* __restrict__ outbuf)
{
    __shared__ __align__(16) float sAr[8][64], sAi[8][64], sBr[8][64], sBi[8][64];
    size_t off = (size_t)blockIdx.z * (NS * NS);
    int row0 = blockIdx.y * 64, col0 = blockIdx.x * 64;
    int tx = threadIdx.x, ty = threadIdx.y;
    int tid = ty * 16 + tx;
    float aR[4][4], aI[4][4];
#pragma unroll
    for (int r = 0; r < 4; r++)
#pragma unroll
        for (int c = 0; c < 4; c++) { aR[r][c] = 0.f; aI[r][c] = 0.f; }

    for (int k0 = 0; k0 < NS; k0 += 8) {
        for (int t = tid; t < 512; t += 256) {
            int kk = t >> 6, r = t & 63;
            int gk = k0 + kk;
            int gi = row0 + r;
            float ar = 0.f, ai = 0.f;
            if (gi < NS && gk < NS) {
                if constexpr (MODE == 1 || MODE == 3) {
                    ar = g_Cm[gi * NS + gk];
                    ai = (MODE == 1) ? -g_Sm[gi * NS + gk] : g_Sm[gi * NS + gk];
                } else {
                    size_t o = off + (size_t)gi * NS + gk;
                    ar = Xr[o]; ai = Xi[o];
                }
            }
            sAr[kk][r] = ar; sAi[kk][r] = ai;
            int gj = col0 + r;
            float br = 0.f, bi = 0.f;
            if (gj < NS && gk < NS) {
                if constexpr (MODE == 1) {
                    br = Xr[off + (size_t)gk * NS + gj];
                } else if constexpr (MODE == 3) {
                    size_t o = off + (size_t)gk * NS + gj;
                    br = Xr[o]; bi = Xi[o];
                } else {
                    br = g_Cm[gk * NS + gj];
                    bi = (MODE == 2) ? -g_Sm[gk * NS + gj] : g_Sm[gk * NS + gj];
                }
            }
            sBr[kk][r] = br;
            if constexpr (MODE != 1) sBi[kk][r] = bi;
        }
        __syncthreads();
#pragma unroll
        for (int kk = 0; kk < 8; kk++) {
            float4 a4r = *(const float4*)&sAr[kk][ty * 4];
            float4 a4i = *(const float4*)&sAi[kk][ty * 4];
            float4 b4r = *(const float4*)&sBr[kk][tx * 4];
            float ar[4] = {a4r.x, a4r.y, a4r.z, a4r.w};
            float ai[4] = {a4i.x, a4i.y, a4i.z, a4i.w};
            float br[4] = {b4r.x, b4r.y, b4r.z, b4r.w};
            if constexpr (MODE == 1) {
#pragma unroll
                for (int r = 0; r < 4; r++)
#pragma unroll
                    for (int c = 0; c < 4; c++) {
                        aR[r][c] += ar[r] * br[c];
                        aI[r][c] += ai[r] * br[c];
                    }
            } else {
                float4 b4i = *(const float4*)&sBi[kk][tx * 4];
                float bi[4] = {b4i.x, b4i.y, b4i.z, b4i.w};
                if constexpr (MODE == 4) {
#pragma unroll
                    for (int r = 0; r < 4; r++)
#pragma unroll
                        for (int c = 0; c < 4; c++)
                            aR[r][c] += ar[r] * br[c] - ai[r] * bi[c];
                } else {
#pragma unroll
                    for (int r = 0; r < 4; r++)
#pragma unroll
                        for (int c = 0; c < 4; c++) {
                            aR[r][c] += ar[r] * br[c] - ai[r] * bi[c];
                            aI[r][c] += ar[r] * bi[c] + ai[r] * br[c];
                        }
                }
            }
        }
        __syncthreads();
    }

    float fw0 = 0.f, fw1 = 0.f;
    if constexpr (MODE == 4) {
        float w0 = fmaxf(gbw[0], 0.f), w1 = fmaxf(gbw[1], 0.f);
        float d = w0 + w1 + 1e-8f;
        fw0 = (w0 / d) * (1.0f / (126.0f * 126.0f));
        fw1 = w1 / d;
    }
#pragma unroll
    for (int r = 0; r < 4; r++)
#pragma unroll
        for (int c = 0; c < 4; c++) {
            int gi = row0 + ty * 4 + r, gj = col0 + tx * 4 + c;
            if (gi < NS && gj < NS) {
                size_t o = off + (size_t)gi * NS + gj;
                if constexpr (MODE == 2) {
                    int su = (gi < 63) ? gi : gi - NS;
                    int sv = (gj < 63) ? gj : gj - NS;
                    float rr = aR[r][c], ii = aI[r][c];
                    float s = (su * su + sv * sv > 1600)
                                  ? sqrtf(rr * rr + ii * ii) : 0.f;
                    Cr[o] = rr * s; Ci[o] = ii * s;
                } else if constexpr (MODE == 4) {
                    outbuf[o] = fw0 * fabsf(aR[r][c]) + fw1 * xcIn[o];
                } else {
                    Cr[o] = aR[r][c]; Ci[o] = aI[r][c];
                }
            }
        }
}

// ---------------- maxpools ----------------
__global__ void mp21_k(const float* __restrict__ in, float* __restrict__ out)
{
    int idx = blockIdx.x * blockDim.x + threadIdx.x;
    int n = NIMG * 125 * 125;
    if (idx >= n) return;
    int w = idx % 125, h = (idx / 125) % 125, ch = idx / (125 * 125);
    const float* p = in + (size_t)ch * NS * NS + (size_t)h * NS + w;
    out[idx] = fmaxf(fmaxf(p[0], p[1]), fmaxf(p[NS], p[NS + 1]));
}
__global__ void mp22_k(const float* __restrict__ in, float* __restrict__ out)
{
    int idx = blockIdx.x * blockDim.x + threadIdx.x;
    int n = NIMG * 31 * 31;
    if (idx >= n) return;
    int w = idx % 31, h = (idx / 31) % 31, ch = idx / (31 * 31);
    const float* p = in + (size_t)ch * 62 * 62 + (size_t)(2 * h) * 62 + 2 * w;
    out[idx] = fmaxf(fmaxf(p[0], p[1]), fmaxf(p[62], p[63]));
}

// ---------------- bilinear resize 31 -> 128 ----------------
__global__ void resize_k(const float* __restrict__ in, float* __restrict__ out)
{
    int idx = blockIdx.x * blockDim.x + threadIdx.x;
    int n = NIMG * HW128 * HW128;
    if (idx >= n) return;
    int x = idx & 127, y = (idx >> 7) & 127, ch = idx >> 14;
    const float sc = 31.f / 128.f;
    float sy = fminf(fmaxf((y + 0.5f) * sc - 0.5f, 0.f), 30.f);
    float sx = fminf(fmaxf((x + 0.5f) * sc - 0.5f, 0.f), 30.f);
    int y0 = (int)floorf(sy); float fy = sy - y0; int y1 = min(y0 + 1, 30);
    int x0 = (int)floorf(sx); float fx = sx - x0; int x1 = min(x0 + 1, 30);
    const float* p = in + (size_t)ch * 961;
    float v = (1.f - fy) * ((1.f - fx) * p[y0 * 31 + x0] + fx * p[y0 * 31 + x1])
            + fy         * ((1.f - fx) * p[y1 * 31 + x0] + fx * p[y1 * 31 + x1]);
    out[idx] = v;
}

// ---------------- log_softmax over channels ----------------
__global__ void lsm_k(const float* __restrict__ in, float* __restrict__ out)
{
    int gid = blockIdx.x * blockDim.x + threadIdx.x;
    if (gid >= NB * HW128 * HW128) return;
    int b = gid >> 14, p = gid & 16383;
    size_t base = (size_t)b * NC * 16384 + p;
    float mx = -1e30f;
    for (int c = 0; c < NC; c++) mx = fmaxf(mx, in[base + (size_t)c * 16384]);
    float s = 0.f;
    for (int c = 0; c < NC; c++) s += expf(in[base + (size_t)c * 16384] - mx);
    float l = logf(s);
    for (int c = 0; c < NC; c++) {
        size_t o = base + (size_t)c * 16384;
        out[o] = in[o] - mx - l;
    }
}

// ---------------- windowed attention ----------------
__global__ void attn_k(const float* __restrict__ qkv, const float* __restrict__ rpb,
                       const int* __restrict__ relidx, float* __restrict__ o)
{
    __shared__ float sk[64][8];
    __shared__ float sv[64][8];
    int win = blockIdx.x;
    int gh = win >> 4, gw = win & 15;
    int n = blockIdx.y, b = blockIdx.z;
    int i = threadIdx.x;
    int hi = gh * 8 + (i >> 3), wi = gw * 8 + (i & 7);
    float q[8];
#pragma unroll
    for (int d = 0; d < 8; d++) {
        int cq = n * 8 + d;
        size_t sp = (size_t)hi * 128 + wi;
        q[d]      = qkv[(((size_t)b * 192 + cq)       * 16384) + sp];
        sk[i][d]  = qkv[(((size_t)b * 192 + 64 + cq)  * 16384) + sp];
        sv[i][d]  = qkv[(((size_t)b * 192 + 128 + cq) * 16384) + sp];
    }
    __syncthreads();
    float logits[64];
    float mx = -1e30f;
#pragma unroll
    for (int j = 0; j < 64; j++) {
        float dot = 0.f;
#pragma unroll
        for (int d = 0; d < 8; d++) dot += q[d] * sk[j][d];
        float l = dot * ATTN_SCALE + rpb[relidx[i * 64 + j] * 8 + n];
        logits[j] = l;
        mx = fmaxf(mx, l);
    }
    float se = 0.f;
#pragma unroll
    for (int j = 0; j < 64; j++) { float e = expf(logits[j] - mx); logits[j] = e; se += e; }
    float inv = 1.f / se;
    float od[8];
#pragma unroll
    for (int d = 0; d < 8; d++) od[d] = 0.f;
#pragma unroll
    for (int j = 0; j < 64; j++) {
#pragma unroll
        for (int d = 0; d < 8; d++) od[d] += logits[j] * sv[j][d];
    }
#pragma unroll
    for (int d = 0; d < 8; d++)
        o[(((size_t)b * 64 + n * 8 + d) * 128 + hi) * 128 + wi] = od[d] * inv;
}

// ---------------- directional pools + add local ----------------
__global__ void poolsum_k(const float* __restrict__ o, const float* __restrict__ loc,
                          float* __restrict__ out)
{
    int idx = blockIdx.x * blockDim.x + threadIdx.x;
    int n = NB * NC * HW128 * HW128;
    if (idx >= n) return;
    int w = idx & 127, h = (idx >> 7) & 127;
    size_t chbase = (size_t)(idx >> 14) * 16384;
    float sx = 0.f;
#pragma unroll
    for (int t = -3; t <= 4; t++) {
        int r = h + t;
        if (r >= 0 && r <= 128) { if (r == 128) r = 126; sx += o[chbase + (size_t)r * 128 + w]; }
    }
    float sy = 0.f;
#pragma unroll
    for (int t = -3; t <= 4; t++) {
        int c = w + t;
        if (c >= 0 && c <= 128) { if (c == 128) c = 126; sy += o[chbase + (size_t)h * 128 + c]; }
    }
    out[idx] = (sx + sy) * 0.125f + loc[idx];
}

// ---------------- depthwise 8x8 conv + BN ----------------
__global__ void dwconv_k(const float* __restrict__ in, const float* __restrict__ w,
                         const float* __restrict__ bng, const float* __restrict__ bnb,
                         float* __restrict__ out)
{
    __shared__ float sIn[23 * 23];
    __shared__ float sWt[64];
    int tile = blockIdx.x;
    int tX = tile & 7, tY = tile >> 3;
    int c = blockIdx.y, b = blockIdx.z;
    int tid = threadIdx.y * 16 + threadIdx.x;
    if (tid < 64) sWt[tid] = w[c * 64 + tid];
    int h0 = tY * 16 - 3, w0 = tX * 16 - 3;
    const float* ip = in + (size_t)(b * 64 + c) * 16384;
    for (int t = tid; t < 23 * 23; t += 256) {
        int iy = t / 23, ix = t - iy * 23;
        int gy = h0 + iy, gx = w0 + ix;
        sIn[t] = (gy >= 0 && gy < 128 && gx >= 0 && gx < 128) ? ip[(size_t)gy * 128 + gx] : 0.f;
    }
    __syncthreads();
    float acc = 0.f;
#pragma unroll
    for (int i = 0; i < 8; i++)
#pragma unroll
        for (int j = 0; j < 8; j++)
            acc += sIn[(threadIdx.y + i) * 23 + threadIdx.x + j] * sWt[i * 8 + j];
    float v = acc * (bng[c] * BN_SC) + bnb[c];
    out[((size_t)(b * 64 + c) * 128 + tY * 16 + threadIdx.y) * 128 + tX * 16 + threadIdx.x] = v;
}

// ---------------- host ----------------
extern "C" void kernel_launch(void* const* d_in, const int* in_sizes, int n_in,
                              void* d_out, int out_size)
{
    const float* x       = (const float*)d_in[0];
    const float* w_qkv   = (const float*)d_in[1];
    const float* w_l1    = (const float*)d_in[2];
    const float* gl1     = (const float*)d_in[3];
    const float* bl1     = (const float*)d_in[4];
    const float* w_l2    = (const float*)d_in[5];
    const float* gl2     = (const float*)d_in[6];
    const float* bl2     = (const float*)d_in[7];
    const float* f_cos   = (const float*)d_in[8];
    const float* f_sin   = (const float*)d_in[9];
    const float* gb_b1   = (const float*)d_in[10];
    const float* gb_b2   = (const float*)d_in[11];
    const float* gb_w    = (const float*)d_in[12];
    const float* w_post  = (const float*)d_in[13];
    const float* g_postp = (const float*)d_in[14];
    const float* b_postp = (const float*)d_in[15];
    const float* w_gc    = (const float*)d_in[16];
    const float* b_gc    = (const float*)d_in[17];
    const float* w_gc1   = (const float*)d_in[18];
    const float* b_gc1   = (const float*)d_in[19];
    const float* w_gc2   = (const float*)d_in[20];
    const float* b_gc2   = (const float*)d_in[21];
    const float* rpb     = (const float*)d_in[22];
    const float* w_dw    = (const float*)d_in[23];
    const float* g_proj  = (const float*)d_in[24];
    const float* b_proj  = (const float*)d_in[25];
    const float* w_pw    = (const float*)d_in[26];
    const int*   relidx  = (const int*)  d_in[27];
    float* out = (float*)d_out;

    float *loc, *qkv, *obuf, *sum, *dw, *xc, *xc2, *cr1, *ci1, *cr2, *ci2;
    float *pb, *qb, *rb, *sb, *tb, *ub, *vb, *wl, *bl, *wgab, *bgab;
    uint32_t *wPH, *wPL;
    cudaGetSymbolAddress((void**)&loc,  g_local);
    cudaGetSymbolAddress((void**)&qkv,  g_qkv);
    cudaGetSymbolAddress((void**)&obuf, g_o);
    cudaGetSymbolAddress((void**)&sum,  g_sum);
    cudaGetSymbolAddress((void**)&dw,   g_dw);
    cudaGetSymbolAddress((void**)&xc,   g_xc);
    cudaGetSymbolAddress((void**)&xc2,  g_xc2);
    cudaGetSymbolAddress((void**)&cr1,  g_cr1);
    cudaGetSymbolAddress((void**)&ci1,  g_ci1);
    cudaGetSymbolAddress((void**)&cr2,  g_cr2);
    cudaGetSymbolAddress((void**)&ci2,  g_ci2);
    cudaGetSymbolAddress((void**)&pb,   g_p);
    cudaGetSymbolAddress((void**)&qb,   g_q);
    cudaGetSymbolAddress((void**)&rb,   g_r);
    cudaGetSymbolAddress((void**)&sb,   g_s);
    cudaGetSymbolAddress((void**)&tb,   g_t);
    cudaGetSymbolAddress((void**)&ub,   g_u);
    cudaGetSymbolAddress((void**)&vb,   g_v);
    cudaGetSymbolAddress((void**)&wl,   g_wl);
    cudaGetSymbolAddress((void**)&bl,   g_bl);
    cudaGetSymbolAddress((void**)&wgab, g_wgab);
    cudaGetSymbolAddress((void**)&bgab, g_bgab);
    cudaGetSymbolAddress((void**)&wPH,  g_wPH);
    cudaGetSymbolAddress((void**)&wPL,  g_wPL);

    const int T = 256;
    // smem: 4*WCH + ICH words + 2*ICH floats
    const int SM3 = (4 * 9 * 512 + 3 * 8 * 424) * 4;   // 114,432 B
    const int SM1 = (4 * 1 * 512 + 3 * 8 * 136) * 4;   // 21,248 B
    cudaFuncSetAttribute(conv_bf<3>, cudaFuncAttributeMaxDynamicSharedMemorySize, SM3);
    cudaFuncSetAttribute(conv_bf<1>, cudaFuncAttributeMaxDynamicSharedMemorySize, SM1);

    // weight prep + DFT tables
    prep_l_k<<<(64*64*9 + T - 1)/T, T>>>(w_l1, gl1, bl1, w_l2, gl2, bl2);
    prep_gab_k<<<(64*64*9 + T - 1)/T, T>>>(f_cos, f_sin, gb_b1, gb_b2);
    prep_wP_k<<<(64*64*9 + T - 1)/T, T>>>(wl,     wPH + WT_L,    wPL + WT_L,    64, 9);
    prep_wP_k<<<(64*64*9 + T - 1)/T, T>>>(wgab,   wPH + WT_GAB,  wPL + WT_GAB,  64, 9);
    prep_wP_k<<<(64*64*9 + T - 1)/T, T>>>(w_post, wPH + WT_POST, wPL + WT_POST, 64, 9);
    prep_wP_k<<<(64*64*9 + T - 1)/T, T>>>(w_gc1,  wPH + WT_GC1,  wPL + WT_GC1,  64, 9);
    prep_wP_k<<<(64*64   + T - 1)/T, T>>>(w_gc2,  wPH + WT_GC2,  wPL + WT_GC2,  64, 1);
    prep_wP_k<<<(192*64  + T - 1)/T, T>>>(w_qkv,  wPH + WT_QKV,  wPL + WT_QKV, 192, 1);
    prep_wP_k<<<(64*64   + T - 1)/T, T>>>(w_pw,   wPH + WT_PW,   wPL + WT_PW,   64, 1);
    initdft_k<<<(NS*NS + T - 1)/T, T>>>();

    // local pre (merged l1+l2)
    conv_bf<3><<<dim3(128,1,NB), 256, SM3>>>(x, wPH + WT_L, wPL + WT_L, bl, nullptr, nullptr,
                                             loc, 128,128, 64,0, 1, 128,128, 0);
    // merged gabor conv (valid, 128->126)
    conv_bf<3><<<dim3(126,1,NB), 256, SM3>>>(loc, wPH + WT_GAB, wPL + WT_GAB, bgab, nullptr,
                                             nullptr, xc, 128,128, 64,0, 0, 126,126, 0);
    // DFT high-pass
    dim3 gg(2, 2, NIMG), bbk(16, 16);
    cgemm_t<1><<<gg, bbk>>>(xc,  nullptr, cr1, ci1, nullptr, nullptr, nullptr);
    cgemm_t<2><<<gg, bbk>>>(cr1, ci1,     cr2, ci2, nullptr, nullptr, nullptr);
    cgemm_t<3><<<gg, bbk>>>(cr2, ci2,     cr1, ci1, nullptr, nullptr, nullptr);
    cgemm_t<4><<<gg, bbk>>>(cr1, ci1,     nullptr, nullptr, xc, gb_w, xc2);
    // post conv + bn + relu6
    conv_bf<3><<<dim3(126,1,NB), 256, SM3>>>(xc2, wPH + WT_POST, wPL + WT_POST, nullptr,
                                             g_postp, b_postp, pb, 126,126, 64,0, 1, 126,126, 2);
    mp21_k<<<(NIMG*125*125 + T - 1)/T, T>>>(pb, qb);
    conv_t<3,2><<<dim3(4, 8, NB), T>>>(qb, w_gc, b_gc, nullptr, nullptr, rb,
                                       125,125, 64,64,0, 0, 62,62, 1,0);
    mp22_k<<<(NIMG*31*31 + T - 1)/T, T>>>(rb, sb);
    resize_k<<<(NIMG*16384 + T - 1)/T, T>>>(sb, tb);
    conv_bf<3><<<dim3(128,1,NB), 256, SM3>>>(tb, wPH + WT_GC1, wPL + WT_GC1, b_gc1, nullptr,
                                             nullptr, ub, 128,128, 64,0, 1, 128,128, 1);
    conv_bf<1><<<dim3(128,1,NB), 256, SM1>>>(ub, wPH + WT_GC2, wPL + WT_GC2, b_gc2, nullptr,
                                             nullptr, vb, 128,128, 64,0, 0, 128,128, 0);
    lsm_k<<<(NB*16384 + T - 1)/T, T>>>(vb, loc);
    // global branch
    conv_bf<1><<<dim3(128,3,NB), 256, SM1>>>(x, wPH + WT_QKV, wPL + WT_QKV, nullptr, nullptr,
                                             nullptr, qkv, 128,128, 192,0, 0, 128,128, 0);
    attn_k<<<dim3(256, NH_, NB), 64>>>(qkv, rpb, relidx, obuf);
    poolsum_k<<<(NB*NC*16384 + T - 1)/T, T>>>(obuf, loc, sum);
    dwconv_k<<<dim3(64, 64, NB), dim3(16,16)>>>(sum, w_dw, g_proj, b_proj, dw);
    conv_bf<1><<<dim3(128,1,NB), 256, SM1>>>(dw, wPH + WT_PW, wPL + WT_PW, nullptr, nullptr,
                                             nullptr, out, 128,128, 64,0, 0, 128,128, 0);
    (void)in_sizes; (void)n_in; (void)out_size;
}

// round 11
// speedup vs baseline: 2.2523x; 1.2260x over previous
#include <cuda_runtime.h>
#include <cuda_bf16.h>
#include <math.h>
#include <cstddef>
#include <cstdint>

// ---------------- constants ----------------
#define BN_SC 0.9999950000374997f   // 1/sqrt(1+1e-5) as float
#define NB 8
#define NC 64
#define NH_ 8
#define HW128 128
#define NS 126
#define NIMG (NB*NC)                 // 512
#define ATTN_SCALE 0.35355339059327373f
#define HOFF (64*NS)                 // half-spectrum buffer stride per image

// ---------------- scratch ----------------
__device__ float g_local[NB*NC*HW128*HW128];
__device__ float g_qkv [NB*3*NC*HW128*HW128];
__device__ float g_o   [NB*NC*HW128*HW128];
__device__ float g_sum [NB*NC*HW128*HW128];
__device__ float g_dw  [NB*NC*HW128*HW128];
__device__ float g_xc  [NIMG*NS*NS];
__device__ float g_xc2 [NIMG*NS*NS];
__device__ float g_cr1 [NIMG*NS*NS];
__device__ float g_ci1 [NIMG*NS*NS];
__device__ float g_cr2 [NIMG*NS*NS];
__device__ float g_ci2 [NIMG*NS*NS];
__device__ float g_p   [NIMG*NS*NS];
__device__ float g_q   [NIMG*125*125];
__device__ float g_r   [NIMG*62*62];
__device__ float g_s   [NIMG*31*31];
__device__ float g_t   [NB*NC*HW128*HW128];
__device__ float g_u   [NB*NC*HW128*HW128];
__device__ float g_v   [NB*NC*HW128*HW128];
__device__ float g_Cm  [NS*NS];
__device__ float g_Sm  [NS*NS];
__device__ float g_wl  [64*64*9];
__device__ float g_bl  [64];
__device__ float g_wgab[64*64*9];
__device__ float g_bgab[64];
// packed bf16x2 duplicated weights (hi plane + lo plane)
__device__ uint32_t g_wPH[167936];
__device__ uint32_t g_wPL[167936];
#define WT_L    0
#define WT_GAB  36864
#define WT_POST 73728
#define WT_GC1  110592
#define WT_GC2  147456
#define WT_QKV  151552
#define WT_PW   163840

__device__ __forceinline__ uint32_t bf_dup(float v)
{
    __nv_bfloat16 h = __float2bfloat16(v);
    uint32_t u = (uint32_t)__bfloat16_as_ushort(h);
    return u | (u << 16);
}

// ---------------- weight-prep kernels ----------------
__global__ void prep_l_k(const float* __restrict__ w1, const float* __restrict__ gg1,
                         const float* __restrict__ bb1, const float* __restrict__ w2,
                         const float* __restrict__ gg2, const float* __restrict__ bb2)
{
    int idx = blockIdx.x * blockDim.x + threadIdx.x;
    if (idx < 64*64*9) {
        int co = idx / (64*9);
        int rem = idx - co * (64*9);
        int ci = rem / 9, k = rem - ci * 9;
        float v = w1[idx] * (gg1[co] * BN_SC);
        if (k == 4) v += w2[co*64 + ci] * (gg2[co] * BN_SC);
        g_wl[idx] = v;
    }
    if (idx < 64) g_bl[idx] = bb1[idx] + bb2[idx];
}

__global__ void prep_gab_k(const float* __restrict__ fc, const float* __restrict__ fs,
                           const float* __restrict__ bc, const float* __restrict__ bs)
{
    int idx = blockIdx.x * blockDim.x + threadIdx.x;
    if (idx < 64*64*9) {
        int co = idx / (64*9);
        g_wgab[idx] = (co < 32) ? fc[idx] : fs[idx - 32*64*9];
    }
    if (idx < 64) g_bgab[idx] = (idx < 32) ? bc[idx] : bs[idx - 32];
}

// fused: all weight tensors -> bf16x2 dup hi/lo planes in one launch
__global__ void prep_all_k(const float* __restrict__ wpost, const float* __restrict__ wgc1,
                           const float* __restrict__ wgc2, const float* __restrict__ wqkv,
                           const float* __restrict__ wpw)
{
    int idx = blockIdx.x * blockDim.x + threadIdx.x;
    if (idx >= 167936) return;
    const float* src; int Cout, KK, base, li;
    if (idx < 36864)        { src = g_wl;   Cout = 64;  KK = 9; base = WT_L;    li = idx; }
    else if (idx < 73728)   { src = g_wgab; Cout = 64;  KK = 9; base = WT_GAB;  li = idx - 36864; }
    else if (idx < 110592)  { src = wpost;  Cout = 64;  KK = 9; base = WT_POST; li = idx - 73728; }
    else if (idx < 147456)  { src = wgc1;   Cout = 64;  KK = 9; base = WT_GC1;  li = idx - 110592; }
    else if (idx < 151552)  { src = wgc2;   Cout = 64;  KK = 1; base = WT_GC2;  li = idx - 147456; }
    else if (idx < 163840)  { src = wqkv;   Cout = 192; KK = 1; base = WT_QKV;  li = idx - 151552; }
    else                    { src = wpw;    Cout = 64;  KK = 1; base = WT_PW;   li = idx - 163840; }
    int co = li / (64 * KK);
    int rem = li - co * (64 * KK);
    int ci = rem / KK, kp = rem - ci * KK;
    int cc = co >> 6, col = co & 63;
    int g = ci >> 3, cil = ci & 7;
    float v = src[li];
    __nv_bfloat16 h = __float2bfloat16(v);
    float lo = v - __bfloat162float(h);
    size_t o = (size_t)base + (((size_t)cc * 8 + g) * KK + kp) * 512 + col * 8 + cil;
    g_wPH[o] = bf_dup(v);
    g_wPL[o] = bf_dup(lo);
    (void)Cout;
}

// ---------------- tensor-core implicit-GEMM conv (split-bf16, exact dup-pair) ----
template<int K>
__global__ void __launch_bounds__(256)
conv_bf(const float* __restrict__ in, const uint32_t* __restrict__ wH,
        const uint32_t* __restrict__ wL,
        const float* __restrict__ bias, const float* __restrict__ bng,
        const float* __restrict__ bnb, float* __restrict__ out,
        int Hin, int Win, int CoutTotal, int coOff, int pad,
        int Hout, int Wout, int act)
{
    constexpr int KK = K * K;
    constexpr int RW = (K == 3) ? 132 : 136;
    constexpr int PSTR = (K == 3) ? 424 : 136;
    constexpr int ICH = 8 * PSTR;
    constexpr int WCH = KK * 512;
    constexpr int JW = (K == 3) ? 130 : 128;

    extern __shared__ uint32_t smemU[];
    uint32_t* sW  = smemU;
    float*    sSt = (float*)(smemU + 4 * WCH);
    uint32_t* sPk = smemU + 4 * WCH + 2 * ICH;

    int r0 = blockIdx.x;
    int cc = blockIdx.y;
    int b  = blockIdx.z;
    int tid = threadIdx.x;
    int warp = tid >> 5, lane = tid & 31;
    int wm = warp & 3, wn = warp >> 2;
    int gid = lane >> 2, tig = lane & 3;
    int m0 = wm * 16, n0 = wn * 64;

    const float* inb = in + (size_t)b * 64 * Hin * Win;
    const uint32_t* wHb = wH + (size_t)cc * (64 * 64 * KK);
    const uint32_t* wLb = wL + (size_t)cc * (64 * 64 * KK);

    auto loadGroup = [&](int g, int buf) {
        uint32_t wdst = (uint32_t)__cvta_generic_to_shared(&sW[buf * 2 * WCH]);
        const uint32_t* whs = wHb + (size_t)g * WCH;
        const uint32_t* wls = wLb + (size_t)g * WCH;
        for (int i = tid; i < WCH / 4; i += 256) {
            asm volatile("cp.async.cg.shared.global [%0], [%1], 16;"
                         :: "r"(wdst + i * 16), "l"(whs + i * 4));
            asm volatile("cp.async.cg.shared.global [%0], [%1], 16;"
                         :: "r"(wdst + (WCH + i * 4) * 4), "l"(wls + i * 4));
        }
        uint32_t idst = (uint32_t)__cvta_generic_to_shared(&sSt[buf * ICH]);
        int ci0 = g * 8;
        int total = 8 * K * JW;
        for (int t = tid; t < total; t += 256) {
            int ci = t / (K * JW);
            int rem = t - ci * (K * JW);
            int ky = rem / JW;
            int j = rem - ky * JW;
            int gy = r0 + ky - pad;
            int gx = j - pad;
            int valid = (gy >= 0 && gy < Hin && gx >= 0 && gx < Win) ? 4 : 0;
            const float* src = inb + (size_t)(ci0 + ci) * Hin * Win;
            const float* gp = valid ? (src + (size_t)gy * Win + gx) : src;
            uint32_t d = idst + (uint32_t)((ci * PSTR + ky * RW + j) * 4);
            asm volatile("cp.async.ca.shared.global [%0], [%1], 4, %2;"
                         :: "r"(d), "l"(gp), "r"(valid));
        }
        asm volatile("cp.async.commit_group;");
    };

    float acc[8][4];
#pragma unroll
    for (int nt = 0; nt < 8; nt++)
#pragma unroll
        for (int i = 0; i < 4; i++) acc[nt][i] = 0.f;

    loadGroup(0, 0);
    for (int g = 0; g < 8; g++) {
        asm volatile("cp.async.wait_group 0;" ::: "memory");
        __syncthreads();
        {
            const float* ps = &sSt[(g & 1) * ICH];
            for (int i = tid; i < ICH; i += 256) {
                float v = ps[i];
                __nv_bfloat16 h = __float2bfloat16(v);
                float lo = v - __bfloat162float(h);
                __nv_bfloat16 l = __float2bfloat16(lo);
                sPk[i] = (uint32_t)__bfloat16_as_ushort(h)
                       | ((uint32_t)__bfloat16_as_ushort(l) << 16);
            }
        }
        __syncthreads();
        if (g < 7) loadGroup(g + 1, (g + 1) & 1);
        const uint32_t* WHp = &sW[(g & 1) * 2 * WCH];
        const uint32_t* WLp = WHp + WCH;
#pragma unroll
        for (int kp = 0; kp < KK; kp++) {
            int ky = kp / K, kx = kp - ky * K;
            const uint32_t* wkh = WHp + kp * 512;
            const uint32_t* wkl = WLp + kp * 512;
            uint32_t ah0 = wkh[(m0 + gid) * 8 + tig];
            uint32_t ah1 = wkh[(m0 + gid + 8) * 8 + tig];
            uint32_t ah2 = wkh[(m0 + gid) * 8 + tig + 4];
            uint32_t ah3 = wkh[(m0 + gid + 8) * 8 + tig + 4];
            uint32_t al0 = wkl[(m0 + gid) * 8 + tig];
            uint32_t al1 = wkl[(m0 + gid + 8) * 8 + tig];
            uint32_t al2 = wkl[(m0 + gid) * 8 + tig + 4];
            uint32_t al3 = wkl[(m0 + gid + 8) * 8 + tig + 4];
            const uint32_t* pb0 = sPk + tig * PSTR + ky * RW + kx + n0 + gid;
            const uint32_t* pb1 = sPk + (tig + 4) * PSTR + ky * RW + kx + n0 + gid;
#pragma unroll
            for (int nt = 0; nt < 8; nt++) {
                uint32_t b0 = pb0[nt * 8];
                uint32_t b1 = pb1[nt * 8];
                asm volatile(
                    "mma.sync.aligned.m16n8k16.row.col.f32.bf16.bf16.f32 "
                    "{%0,%1,%2,%3}, {%4,%5,%6,%7}, {%8,%9}, {%0,%1,%2,%3};"
                    : "+f"(acc[nt][0]), "+f"(acc[nt][1]), "+f"(acc[nt][2]), "+f"(acc[nt][3])
                    : "r"(ah0), "r"(ah1), "r"(ah2), "r"(ah3), "r"(b0), "r"(b1));
                asm volatile(
                    "mma.sync.aligned.m16n8k16.row.col.f32.bf16.bf16.f32 "
                    "{%0,%1,%2,%3}, {%4,%5,%6,%7}, {%8,%9}, {%0,%1,%2,%3};"
                    : "+f"(acc[nt][0]), "+f"(acc[nt][1]), "+f"(acc[nt][2]), "+f"(acc[nt][3])
                    : "r"(al0), "r"(al1), "r"(al2), "r"(al3), "r"(b0), "r"(b1));
            }
        }
        __syncthreads();
    }

    int coA = cc * 64 + m0 + gid;
    int coB = coA + 8;
    float biA = bias ? bias[coA] : 0.f;
    float biB = bias ? bias[coB] : 0.f;
    float scA = 1.f, shA = 0.f, scB = 1.f, shB = 0.f;
    if (bng) {
        scA = bng[coA] * BN_SC; shA = bnb[coA];
        scB = bng[coB] * BN_SC; shB = bnb[coB];
    }
    size_t rowA = ((size_t)(b * CoutTotal + coOff + coA) * Hout + r0) * Wout;
    size_t rowB = ((size_t)(b * CoutTotal + coOff + coB) * Hout + r0) * Wout;
#pragma unroll
    for (int nt = 0; nt < 8; nt++) {
        int nb = n0 + nt * 8 + 2 * tig;
        if (nb >= Wout) continue;
        float v0 = acc[nt][0] + biA, v1 = acc[nt][1] + biA;
        float v2 = acc[nt][2] + biB, v3 = acc[nt][3] + biB;
        if (bng) {
            v0 = v0 * scA + shA; v1 = v1 * scA + shA;
            v2 = v2 * scB + shB; v3 = v3 * scB + shB;
        }
        if (act == 1) {
            v0 = fmaxf(v0, 0.f); v1 = fmaxf(v1, 0.f);
            v2 = fmaxf(v2, 0.f); v3 = fmaxf(v3, 0.f);
        } else if (act == 2) {
            v0 = fminf(fmaxf(v0, 0.f), 6.f); v1 = fminf(fmaxf(v1, 0.f), 6.f);
            v2 = fminf(fmaxf(v2, 0.f), 6.f); v3 = fminf(fmaxf(v3, 0.f), 6.f);
        }
        *(float2*)&out[rowA + nb] = make_float2(v0, v1);
        *(float2*)&out[rowB + nb] = make_float2(v2, v3);
    }
}

// ---------------- fp32 direct conv (kept for stride-2) ----------------
template<int K, int STRIDE>
__global__ void __launch_bounds__(256)
conv_t(const float* __restrict__ in, const float* __restrict__ w,
       const float* __restrict__ bias, const float* __restrict__ bng,
       const float* __restrict__ bnb, float* __restrict__ out,
       int Hin, int Win, int Cout, int CoutTotal, int coOff,
       int pad, int Hout, int Wout, int act, int accum)
{
    constexpr int KK = K * K;
    constexpr int TS = 32;
    constexpr int SPAN = (TS - 1) * STRIDE + K;
    constexpr int R = STRIDE + K;
    __shared__ __align__(16) float sW[64 * KK * 8];
    __shared__ float sIn1[SPAN * SPAN];

    int tileW = (Wout + TS - 1) / TS;
    int tX = blockIdx.x % tileW, tY = blockIdx.x / tileW;
    int ow0 = tX * TS, oh0 = tY * TS;
    int co0 = blockIdx.y << 3;
    int b   = blockIdx.z;
    int tid = threadIdx.x;
    int ty = tid >> 4, tx = tid & 15;

    for (int t = tid; t < 64 * KK * 8; t += 256) {
        int row = t >> 3, co = t & 7;
        int ci = row / KK, kp = row - ci * KK;
        sW[t] = (co0 + co < Cout) ? w[(size_t)(co0 + co) * (64 * KK) + ci * KK + kp] : 0.f;
    }

    int ih0 = oh0 * STRIDE - pad, iw0 = ow0 * STRIDE - pad;
    float acc[8][2][2];
#pragma unroll
    for (int co = 0; co < 8; co++)
#pragma unroll
        for (int oy = 0; oy < 2; oy++)
#pragma unroll
            for (int ox = 0; ox < 2; ox++) acc[co][oy][ox] = 0.f;

    const float* inb = in + (size_t)b * 64 * Hin * Win;
    int base = (ty * 2 * STRIDE) * SPAN + tx * 2 * STRIDE;

    for (int ci = 0; ci < 64; ci++) {
        __syncthreads();
        const float* ip = inb + (size_t)ci * Hin * Win;
        for (int t = tid; t < SPAN * SPAN; t += 256) {
            int iy = t / SPAN, ix = t - iy * SPAN;
            int gy = ih0 + iy, gx = iw0 + ix;
            sIn1[t] = (gy >= 0 && gy < Hin && gx >= 0 && gx < Win)
                          ? __ldg(&ip[(size_t)gy * Win + gx]) : 0.f;
        }
        __syncthreads();
        float xin[R][R];
#pragma unroll
        for (int r = 0; r < R; r++)
#pragma unroll
            for (int c = 0; c < R; c++) xin[r][c] = sIn1[base + r * SPAN + c];
        const float4* wq = reinterpret_cast<const float4*>(&sW[ci * KK * 8]);
#pragma unroll
        for (int kp = 0; kp < KK; kp++) {
            float4 wa = wq[kp * 2], wb = wq[kp * 2 + 1];
            float wv[8] = {wa.x, wa.y, wa.z, wa.w, wb.x, wb.y, wb.z, wb.w};
            int ky = kp / K, kx = kp - ky * K;
#pragma unroll
            for (int oy = 0; oy < 2; oy++)
#pragma unroll
                for (int ox = 0; ox < 2; ox++) {
                    float xv = xin[oy * STRIDE + ky][ox * STRIDE + kx];
#pragma unroll
                    for (int co = 0; co < 8; co++)
                        acc[co][oy][ox] += xv * wv[co];
                }
        }
    }

#pragma unroll
    for (int co = 0; co < 8; co++) {
        int gco = co0 + co;
        if (gco >= Cout) break;
        float bi = bias ? bias[gco] : 0.f;
        float sc = 1.f, sh = 0.f;
        if (bng) { sc = bng[gco] * BN_SC; sh = bnb[gco]; }
#pragma unroll
        for (int oy = 0; oy < 2; oy++) {
            int oh = oh0 + ty * 2 + oy;
            if (oh >= Hout) continue;
#pragma unroll
            for (int ox = 0; ox < 2; ox++) {
                int ow = ow0 + tx * 2 + ox;
                if (ow >= Wout) continue;
                float v = acc[co][oy][ox] + bi;
                if (bng) v = v * sc + sh;
                if (act == 1) v = fmaxf(v, 0.f);
                else if (act == 2) v = fminf(fmaxf(v, 0.f), 6.f);
                size_t oidx = (((size_t)b * CoutTotal + coOff + gco) * Hout + oh) * Wout + ow;
                if (accum) out[oidx] += v; else out[oidx] = v;
            }
        }
    }
}

// ---------------- DFT matrices ----------------
__global__ void initdft_k()
{
    int idx = blockIdx.x * blockDim.x + threadIdx.x;
    if (idx >= NS * NS) return;
    int u = idx / NS, h = idx % NS;
    int m = (u * h) % NS;
    float xx = (2.0f * (float)m) / (float)NS;
    g_Cm[idx] = cospif(xx);
    g_Sm[idx] = sinpif(xx);
}

// ---------------- DFT GEMM stages (Hermitian-halved) ----------------
// Input is real -> spectrum rows u>63 are conjugates of rows 126-u; only rows
// 0..63 are ever computed.  W = F*(G F*) with folded conjugate row pairs.
// MODE 1: Y(64x126)  = F[0:64,:] X            (X real, full)
// MODE 2: Z(64x126)  = Y F        + mask epi  (half -> half)
// MODE 3: T(64x126)  = G F*                   (half -> half)
// MODE 4: W(126x126) = sum_u wgt_u Re(F*[:,u] T[u,:]) + combine epi (K=64)
template<int MODE>
__global__ void __launch_bounds__(256)
cgemm_t(const float* __restrict__ Xr, const float* __restrict__ Xi,
        float* __restrict__ Cr, float* __restrict__ Ci,
        const float* __restrict__ xcIn, const float* __restrict__ gbw,
        float* __restrict__ outbuf)
{
    constexpr int KMAX  = (MODE == 4) ? 64 : NS;
    constexpr int MROWS = (MODE == 4) ? NS : 64;
    __shared__ __align__(16) float sAr[8][64], sAi[8][64], sBr[8][64], sBi[8][64];
    int z = blockIdx.z;
    size_t offIn  = (size_t)z * ((MODE == 1) ? (NS * NS) : HOFF);
    size_t offOut = (size_t)z * ((MODE == 4) ? (NS * NS) : HOFF);
    int row0 = blockIdx.y * 64, col0 = blockIdx.x * 64;
    int tx = threadIdx.x, ty = threadIdx.y;
    int tid = ty * 16 + tx;
    float aR[4][4], aI[4][4];
#pragma unroll
    for (int r = 0; r < 4; r++)
#pragma unroll
        for (int c = 0; c < 4; c++) { aR[r][c] = 0.f; aI[r][c] = 0.f; }

    for (int k0 = 0; k0 < KMAX; k0 += 8) {
        for (int t = tid; t < 512; t += 256) {
            int kk = t >> 6, r = t & 63;
            int gk = k0 + kk;
            int gi = row0 + r;
            float ar = 0.f, ai = 0.f;
            if (gi < MROWS && gk < KMAX) {
                if constexpr (MODE == 1) {
                    ar = g_Cm[gi * NS + gk]; ai = -g_Sm[gi * NS + gk];
                } else if constexpr (MODE == 4) {
                    float wgt = (gk == 0 || gk == 63) ? 1.f : 2.f;
                    ar = wgt * g_Cm[gi * NS + gk];
                    ai = wgt * g_Sm[gi * NS + gk];
                } else {
                    size_t o = offIn + (size_t)gi * NS + gk;
                    ar = Xr[o]; ai = Xi[o];
                }
            }
            sAr[kk][r] = ar; sAi[kk][r] = ai;
            int gj = col0 + r;
            float br = 0.f, bi = 0.f;
            if (gj < NS && gk < KMAX) {
                if constexpr (MODE == 1) {
                    br = Xr[offIn + (size_t)gk * NS + gj];
                } else if constexpr (MODE == 4) {
                    size_t o = offIn + (size_t)gk * NS + gj;
                    br = Xr[o]; bi = Xi[o];
                } else {
                    br = g_Cm[gk * NS + gj];
                    bi = (MODE == 2) ? -g_Sm[gk * NS + gj] : g_Sm[gk * NS + gj];
                }
            }
            sBr[kk][r] = br;
            if constexpr (MODE != 1) sBi[kk][r] = bi;
        }
        __syncthreads();
#pragma unroll
        for (int kk = 0; kk < 8; kk++) {
            float4 a4r = *(const float4*)&sAr[kk][ty * 4];
            float4 a4i = *(const float4*)&sAi[kk][ty * 4];
            float4 b4r = *(const float4*)&sBr[kk][tx * 4];
            float ar[4] = {a4r.x, a4r.y, a4r.z, a4r.w};
            float ai[4] = {a4i.x, a4i.y, a4i.z, a4i.w};
            float br[4] = {b4r.x, b4r.y, b4r.z, b4r.w};
            if constexpr (MODE == 1) {
#pragma unroll
                for (int r = 0; r < 4; r++)
#pragma unroll
                    for (int c = 0; c < 4; c++) {
                        aR[r][c] += ar[r] * br[c];
                        aI[r][c] += ai[r] * br[c];
                    }
            } else {
                float4 b4i = *(const float4*)&sBi[kk][tx * 4];
                float bi[4] = {b4i.x, b4i.y, b4i.z, b4i.w};
                if constexpr (MODE == 4) {
#pragma unroll
                    for (int r = 0; r < 4; r++)
#pragma unroll
                        for (int c = 0; c < 4; c++)
                            aR[r][c] += ar[r] * br[c] - ai[r] * bi[c];
                } else {
#pragma unroll
                    for (int r = 0; r < 4; r++)
#pragma unroll
                        for (int c = 0; c < 4; c++) {
                            aR[r][c] += ar[r] * br[c] - ai[r] * bi[c];
                            aI[r][c] += ar[r] * bi[c] + ai[r] * br[c];
                        }
                }
            }
        }
        __syncthreads();
    }

    float fw0 = 0.f, fw1 = 0.f;
    if constexpr (MODE == 4) {
        float w0 = fmaxf(gbw[0], 0.f), w1 = fmaxf(gbw[1], 0.f);
        float d = w0 + w1 + 1e-8f;
        fw0 = (w0 / d) * (1.0f / (126.0f * 126.0f));
        fw1 = w1 / d;
    }
#pragma unroll
    for (int r = 0; r < 4; r++)
#pragma unroll
        for (int c = 0; c < 4; c++) {
            int gi = row0 + ty * 4 + r, gj = col0 + tx * 4 + c;
            if (gi < MROWS && gj < NS) {
                size_t o = offOut + (size_t)gi * NS + gj;
                if constexpr (MODE == 2) {
                    int su = (gi < 63) ? gi : gi - NS;
                    int sv = (gj < 63) ? gj : gj - NS;
                    float rr = aR[r][c], ii = aI[r][c];
                    float s = (su * su + sv * sv > 1600)
                                  ? sqrtf(rr * rr + ii * ii) : 0.f;
                    Cr[o] = rr * s; Ci[o] = ii * s;
                } else if constexpr (MODE == 4) {
                    outbuf[o] = fw0 * fabsf(aR[r][c])
                              + fw1 * xcIn[(size_t)z * NS * NS + (size_t)gi * NS + gj];
                } else {
                    Cr[o] = aR[r][c]; Ci[o] = aI[r][c];
                }
            }
        }
}

// ---------------- maxpools ----------------
__global__ void mp21_k(const float* __restrict__ in, float* __restrict__ out)
{
    int idx = blockIdx.x * blockDim.x + threadIdx.x;
    int n = NIMG * 125 * 125;
    if (idx >= n) return;
    int w = idx % 125, h = (idx / 125) % 125, ch = idx / (125 * 125);
    const float* p = in + (size_t)ch * NS * NS + (size_t)h * NS + w;
    out[idx] = fmaxf(fmaxf(p[0], p[1]), fmaxf(p[NS], p[NS + 1]));
}
__global__ void mp22_k(const float* __restrict__ in, float* __restrict__ out)
{
    int idx = blockIdx.x * blockDim.x + threadIdx.x;
    int n = NIMG * 31 * 31;
    if (idx >= n) return;
    int w = idx % 31, h = (idx / 31) % 31, ch = idx / (31 * 31);
    const float* p = in + (size_t)ch * 62 * 62 + (size_t)(2 * h) * 62 + 2 * w;
    out[idx] = fmaxf(fmaxf(p[0], p[1]), fmaxf(p[62], p[63]));
}

// ---------------- bilinear resize 31 -> 128 ----------------
__global__ void resize_k(const float* __restrict__ in, float* __restrict__ out)
{
    int idx = blockIdx.x * blockDim.x + threadIdx.x;
    int n = NIMG * HW128 * HW128;
    if (idx >= n) return;
    int x = idx & 127, y = (idx >> 7) & 127, ch = idx >> 14;
    const float sc = 31.f / 128.f;
    float sy = fminf(fmaxf((y + 0.5f) * sc - 0.5f, 0.f), 30.f);
    float sx = fminf(fmaxf((x + 0.5f) * sc - 0.5f, 0.f), 30.f);
    int y0 = (int)floorf(sy); float fy = sy - y0; int y1 = min(y0 + 1, 30);
    int x0 = (int)floorf(sx); float fx = sx - x0; int x1 = min(x0 + 1, 30);
    const float* p = in + (size_t)ch * 961;
    float v = (1.f - fy) * ((1.f - fx) * p[y0 * 31 + x0] + fx * p[y0 * 31 + x1])
            + fy         * ((1.f - fx) * p[y1 * 31 + x0] + fx * p[y1 * 31 + x1]);
    out[idx] = v;
}

// ---------------- log_softmax over channels ----------------
__global__ void lsm_k(const float* __restrict__ in, float* __restrict__ out)
{
    int gid = blockIdx.x * blockDim.x + threadIdx.x;
    if (gid >= NB * HW128 * HW128) return;
    int b = gid >> 14, p = gid & 16383;
    size_t base = (size_t)b * NC * 16384 + p;
    float mx = -1e30f;
    for (int c = 0; c < NC; c++) mx = fmaxf(mx, in[base + (size_t)c * 16384]);
    float s = 0.f;
    for (int c = 0; c < NC; c++) s += expf(in[base + (size_t)c * 16384] - mx);
    float l = logf(s);
    for (int c = 0; c < NC; c++) {
        size_t o = base + (size_t)c * 16384;
        out[o] = in[o] - mx - l;
    }
}

// ---------------- windowed attention ----------------
__global__ void attn_k(const float* __restrict__ qkv, const float* __restrict__ rpb,
                       const int* __restrict__ relidx, float* __restrict__ o)
{
    __shared__ float sk[64][8];
    __shared__ float sv[64][8];
    int win = blockIdx.x;
    int gh = win >> 4, gw = win & 15;
    int n = blockIdx.y, b = blockIdx.z;
    int i = threadIdx.x;
    int hi = gh * 8 + (i >> 3), wi = gw * 8 + (i & 7);
    float q[8];
#pragma unroll
    for (int d = 0; d < 8; d++) {
        int cq = n * 8 + d;
        size_t sp = (size_t)hi * 128 + wi;
        q[d]      = qkv[(((size_t)b * 192 + cq)       * 16384) + sp];
        sk[i][d]  = qkv[(((size_t)b * 192 + 64 + cq)  * 16384) + sp];
        sv[i][d]  = qkv[(((size_t)b * 192 + 128 + cq) * 16384) + sp];
    }
    __syncthreads();
    float logits[64];
    float mx = -1e30f;
#pragma unroll
    for (int j = 0; j < 64; j++) {
        float dot = 0.f;
#pragma unroll
        for (int d = 0; d < 8; d++) dot += q[d] * sk[j][d];
        float l = dot * ATTN_SCALE + rpb[relidx[i * 64 + j] * 8 + n];
        logits[j] = l;
        mx = fmaxf(mx, l);
    }
    float se = 0.f;
#pragma unroll
    for (int j = 0; j < 64; j++) { float e = expf(logits[j] - mx); logits[j] = e; se += e; }
    float inv = 1.f / se;
    float od[8];
#pragma unroll
    for (int d = 0; d < 8; d++) od[d] = 0.f;
#pragma unroll
    for (int j = 0; j < 64; j++) {
#pragma unroll
        for (int d = 0; d < 8; d++) od[d] += logits[j] * sv[j][d];
    }
#pragma unroll
    for (int d = 0; d < 8; d++)
        o[(((size_t)b * 64 + n * 8 + d) * 128 + hi) * 128 + wi] = od[d] * inv;
}

// ---------------- directional pools + add local ----------------
__global__ void poolsum_k(const float* __restrict__ o, const float* __restrict__ loc,
                          float* __restrict__ out)
{
    int idx = blockIdx.x * blockDim.x + threadIdx.x;
    int n = NB * NC * HW128 * HW128;
    if (idx >= n) return;
    int w = idx & 127, h = (idx >> 7) & 127;
    size_t chbase = (size_t)(idx >> 14) * 16384;
    float sx = 0.f;
#pragma unroll
    for (int t = -3; t <= 4; t++) {
        int r = h + t;
        if (r >= 0 && r <= 128) { if (r == 128) r = 126; sx += o[chbase + (size_t)r * 128 + w]; }
    }
    float sy = 0.f;
#pragma unroll
    for (int t = -3; t <= 4; t++) {
        int c = w + t;
        if (c >= 0 && c <= 128) { if (c == 128) c = 126; sy += o[chbase + (size_t)h * 128 + c]; }
    }
    out[idx] = (sx + sy) * 0.125f + loc[idx];
}

// ---------------- depthwise 8x8 conv + BN ----------------
__global__ void dwconv_k(const float* __restrict__ in, const float* __restrict__ w,
                         const float* __restrict__ bng, const float* __restrict__ bnb,
                         float* __restrict__ out)
{
    __shared__ float sIn[23 * 23];
    __shared__ float sWt[64];
    int tile = blockIdx.x;
    int tX = tile & 7, tY = tile >> 3;
    int c = blockIdx.y, b = blockIdx.z;
    int tid = threadIdx.y * 16 + threadIdx.x;
    if (tid < 64) sWt[tid] = w[c * 64 + tid];
    int h0 = tY * 16 - 3, w0 = tX * 16 - 3;
    const float* ip = in + (size_t)(b * 64 + c) * 16384;
    for (int t = tid; t < 23 * 23; t += 256) {
        int iy = t / 23, ix = t - iy * 23;
        int gy = h0 + iy, gx = w0 + ix;
        sIn[t] = (gy >= 0 && gy < 128 && gx >= 0 && gx < 128) ? ip[(size_t)gy * 128 + gx] : 0.f;
    }
    __syncthreads();
    float acc = 0.f;
#pragma unroll
    for (int i = 0; i < 8; i++)
#pragma unroll
        for (int j = 0; j < 8; j++)
            acc += sIn[(threadIdx.y + i) * 23 + threadIdx.x + j] * sWt[i * 8 + j];
    float v = acc * (bng[c] * BN_SC) + bnb[c];
    out[((size_t)(b * 64 + c) * 128 + tY * 16 + threadIdx.y) * 128 + tX * 16 + threadIdx.x] = v;
}

// ---------------- host ----------------
extern "C" void kernel_launch(void* const* d_in, const int* in_sizes, int n_in,
                              void* d_out, int out_size)
{
    const float* x       = (const float*)d_in[0];
    const float* w_qkv   = (const float*)d_in[1];
    const float* w_l1    = (const float*)d_in[2];
    const float* gl1     = (const float*)d_in[3];
    const float* bl1     = (const float*)d_in[4];
    const float* w_l2    = (const float*)d_in[5];
    const float* gl2     = (const float*)d_in[6];
    const float* bl2     = (const float*)d_in[7];
    const float* f_cos   = (const float*)d_in[8];
    const float* f_sin   = (const float*)d_in[9];
    const float* gb_b1   = (const float*)d_in[10];
    const float* gb_b2   = (const float*)d_in[11];
    const float* gb_w    = (const float*)d_in[12];
    const float* w_post  = (const float*)d_in[13];
    const float* g_postp = (const float*)d_in[14];
    const float* b_postp = (const float*)d_in[15];
    const float* w_gc    = (const float*)d_in[16];
    const float* b_gc    = (const float*)d_in[17];
    const float* w_gc1   = (const float*)d_in[18];
    const float* b_gc1   = (const float*)d_in[19];
    const float* w_gc2   = (const float*)d_in[20];
    const float* b_gc2   = (const float*)d_in[21];
    const float* rpb     = (const float*)d_in[22];
    const float* w_dw    = (const float*)d_in[23];
    const float* g_proj  = (const float*)d_in[24];
    const float* b_proj  = (const float*)d_in[25];
    const float* w_pw    = (const float*)d_in[26];
    const int*   relidx  = (const int*)  d_in[27];
    float* out = (float*)d_out;

    float *loc, *qkv, *obuf, *sum, *dw, *xc, *xc2, *cr1, *ci1, *cr2, *ci2;
    float *pb, *qb, *rb, *sb, *tb, *ub, *vb;
    uint32_t *wPH, *wPL;
    cudaGetSymbolAddress((void**)&loc,  g_local);
    cudaGetSymbolAddress((void**)&qkv,  g_qkv);
    cudaGetSymbolAddress((void**)&obuf, g_o);
    cudaGetSymbolAddress((void**)&sum,  g_sum);
    cudaGetSymbolAddress((void**)&dw,   g_dw);
    cudaGetSymbolAddress((void**)&xc,   g_xc);
    cudaGetSymbolAddress((void**)&xc2,  g_xc2);
    cudaGetSymbolAddress((void**)&cr1,  g_cr1);
    cudaGetSymbolAddress((void**)&ci1,  g_ci1);
    cudaGetSymbolAddress((void**)&cr2,  g_cr2);
    cudaGetSymbolAddress((void**)&ci2,  g_ci2);
    cudaGetSymbolAddress((void**)&pb,   g_p);
    cudaGetSymbolAddress((void**)&qb,   g_q);
    cudaGetSymbolAddress((void**)&rb,   g_r);
    cudaGetSymbolAddress((void**)&sb,   g_s);
    cudaGetSymbolAddress((void**)&tb,   g_t);
    cudaGetSymbolAddress((void**)&ub,   g_u);
    cudaGetSymbolAddress((void**)&vb,   g_v);
    cudaGetSymbolAddress((void**)&wPH,  g_wPH);
    cudaGetSymbolAddress((void**)&wPL,  g_wPL);

    const int T = 256;
    const int SM3 = (4 * 9 * 512 + 3 * 8 * 424) * 4;   // 114,432 B
    const int SM1 = (4 * 1 * 512 + 3 * 8 * 136) * 4;   // 21,248 B
    cudaFuncSetAttribute(conv_bf<3>, cudaFuncAttributeMaxDynamicSharedMemorySize, SM3);
    cudaFuncSetAttribute(conv_bf<1>, cudaFuncAttributeMaxDynamicSharedMemorySize, SM1);

    // weight prep + DFT tables
    prep_l_k<<<(64*64*9 + T - 1)/T, T>>>(w_l1, gl1, bl1, w_l2, gl2, bl2);
    prep_gab_k<<<(64*64*9 + T - 1)/T, T>>>(f_cos, f_sin, gb_b1, gb_b2);
    prep_all_k<<<(167936 + T - 1)/T, T>>>(w_post, w_gc1, w_gc2, w_qkv, w_pw);
    initdft_k<<<(NS*NS + T - 1)/T, T>>>();

    // local pre (merged l1+l2)
    conv_bf<3><<<dim3(128,1,NB), 256, SM3>>>(x, wPH + WT_L, wPL + WT_L, g_bl, nullptr, nullptr,
                                             loc, 128,128, 64,0, 1, 128,128, 0);
    // merged gabor conv (valid, 128->126)
    conv_bf<3><<<dim3(126,1,NB), 256, SM3>>>(loc, wPH + WT_GAB, wPL + WT_GAB, g_bgab, nullptr,
                                             nullptr, xc, 128,128, 64,0, 0, 126,126, 0);
    // DFT high-pass (Hermitian-halved): Y=F X(64 rows) -> Z=Y F + mask -> T=G F* -> W=F* T folded
    dim3 bbk(16, 16);
    cgemm_t<1><<<dim3(2,1,NIMG), bbk>>>(xc,  nullptr, cr1, ci1, nullptr, nullptr, nullptr);
    cgemm_t<2><<<dim3(2,1,NIMG), bbk>>>(cr1, ci1,     cr2, ci2, nullptr, nullptr, nullptr);
    cgemm_t<3><<<dim3(2,1,NIMG), bbk>>>(cr2, ci2,     cr1, ci1, nullptr, nullptr, nullptr);
    cgemm_t<4><<<dim3(2,2,NIMG), bbk>>>(cr1, ci1,     nullptr, nullptr, xc, gb_w, xc2);
    // post conv + bn + relu6
    conv_bf<3><<<dim3(126,1,NB), 256, SM3>>>(xc2, wPH + WT_POST, wPL + WT_POST, nullptr,
                                             g_postp, b_postp, pb, 126,126, 64,0, 1, 126,126, 2);
    mp21_k<<<(NIMG*125*125 + T - 1)/T, T>>>(pb, qb);
    conv_t<3,2><<<dim3(4, 8, NB), T>>>(qb, w_gc, b_gc, nullptr, nullptr, rb,
                                       125,125, 64,64,0, 0, 62,62, 1,0);
    mp22_k<<<(NIMG*31*31 + T - 1)/T, T>>>(rb, sb);
    resize_k<<<(NIMG*16384 + T - 1)/T, T>>>(sb, tb);
    conv_bf<3><<<dim3(128,1,NB), 256, SM3>>>(tb, wPH + WT_GC1, wPL + WT_GC1, b_gc1, nullptr,
                                             nullptr, ub, 128,128, 64,0, 1, 128,128, 1);
    conv_bf<1><<<dim3(128,1,NB), 256, SM1>>>(ub, wPH + WT_GC2, wPL + WT_GC2, b_gc2, nullptr,
                                             nullptr, vb, 128,128, 64,0, 0, 128,128, 0);
    lsm_k<<<(NB*16384 + T - 1)/T, T>>>(vb, loc);
    // global branch
    conv_bf<1><<<dim3(128,3,NB), 256, SM1>>>(x, wPH + WT_QKV, wPL + WT_QKV, nullptr, nullptr,
                                             nullptr, qkv, 128,128, 192,0, 0, 128,128, 0);
    attn_k<<<dim3(256, NH_, NB), 64>>>(qkv, rpb, relidx, obuf);
    poolsum_k<<<(NB*NC*16384 + T - 1)/T, T>>>(obuf, loc, sum);
    dwconv_k<<<dim3(64, 64, NB), dim3(16,16)>>>(sum, w_dw, g_proj, b_proj, dw);
    conv_bf<1><<<dim3(128,1,NB), 256, SM1>>>(dw, wPH + WT_PW, wPL + WT_PW, nullptr, nullptr,
                                             nullptr, out, 128,128, 64,0, 0, 128,128, 0);
    (void)in_sizes; (void)n_in; (void)out_size;
}

// round 13
// speedup vs baseline: 2.3771x; 1.0554x over previous
#include <cuda_runtime.h>
#include <cuda_bf16.h>
#include <math.h>
#include <cstddef>
#include <cstdint>

// ---------------- constants ----------------
#define BN_SC 0.9999950000374997f   // 1/sqrt(1+1e-5) as float
#define NB 8
#define NC 64
#define NH_ 8
#define HW128 128
#define NS 126
#define NIMG (NB*NC)                 // 512
#define ATTN_SCALE 0.35355339059327373f

// ---------------- scratch ----------------
__device__ float g_local[NB*NC*HW128*HW128];
__device__ float g_qkv [NB*3*NC*HW128*HW128];
__device__ float g_o   [NB*NC*HW128*HW128];
__device__ float g_sum [NB*NC*HW128*HW128];
__device__ float g_dw  [NB*NC*HW128*HW128];
__device__ float g_xc  [NIMG*NS*NS];
__device__ float g_xc2 [NIMG*NS*NS];
__device__ float g_p   [NIMG*NS*NS];
__device__ float g_q   [NIMG*125*125];
__device__ float g_r   [NIMG*62*62];
__device__ float g_s   [NIMG*31*31];
__device__ float g_t   [NB*NC*HW128*HW128];
__device__ float g_u   [NB*NC*HW128*HW128];
__device__ float g_v   [NB*NC*HW128*HW128];
__device__ float g_Cm  [NS*NS];
__device__ float g_Sm  [NS*NS];
__device__ float g_wl  [64*64*9];
__device__ float g_bl  [64];
__device__ float g_wgab[64*64*9];
__device__ float g_bgab[64];
// packed bf16x2 duplicated weights (hi plane + lo plane)
__device__ __align__(16) uint32_t g_wPH[167936];
__device__ __align__(16) uint32_t g_wPL[167936];
#define WT_L    0
#define WT_GAB  36864
#define WT_POST 73728
#define WT_GC1  110592
#define WT_GC2  147456
#define WT_QKV  151552
#define WT_PW   163840
// DFT fixed matrices, bf16x2 dup hi/lo planes:
// A1 [128][128], A2 [256][256], A3 [256][256], A4 [128][128]
__device__ __align__(16) uint32_t g_AH[163840];
__device__ __align__(16) uint32_t g_AL[163840];
#define A1_OFF 0
#define A2_OFF 16384
#define A3_OFF 81920
#define A4_OFF 147456
// DFT data buffers: YT/ZT [252x64]/img, B4 [128x126]/img
__device__ float g_dft1[NIMG*252*64];
__device__ float g_dft2[NIMG*252*64];
__device__ float g_dft3[NIMG*128*126];

__device__ __forceinline__ uint32_t bf_dup(float v)
{
    __nv_bfloat16 h = __float2bfloat16(v);
    uint32_t u = (uint32_t)__bfloat16_as_ushort(h);
    return u | (u << 16);
}

// ---------------- weight-prep kernels ----------------
__global__ void prep_l_k(const float* __restrict__ w1, const float* __restrict__ gg1,
                         const float* __restrict__ bb1, const float* __restrict__ w2,
                         const float* __restrict__ gg2, const float* __restrict__ bb2)
{
    int idx = blockIdx.x * blockDim.x + threadIdx.x;
    if (idx < 64*64*9) {
        int co = idx / (64*9);
        int rem = idx - co * (64*9);
        int ci = rem / 9, k = rem - ci * 9;
        float v = w1[idx] * (gg1[co] * BN_SC);
        if (k == 4) v += w2[co*64 + ci] * (gg2[co] * BN_SC);
        g_wl[idx] = v;
    }
    if (idx < 64) g_bl[idx] = bb1[idx] + bb2[idx];
}

__global__ void prep_gab_k(const float* __restrict__ fc, const float* __restrict__ fs,
                           const float* __restrict__ bc, const float* __restrict__ bs)
{
    int idx = blockIdx.x * blockDim.x + threadIdx.x;
    if (idx < 64*64*9) {
        int co = idx / (64*9);
        g_wgab[idx] = (co < 32) ? fc[idx] : fs[idx - 32*64*9];
    }
    if (idx < 64) g_bgab[idx] = (idx < 32) ? bc[idx] : bs[idx - 32];
}

// fused: all conv weight tensors -> bf16x2 dup hi/lo planes
__global__ void prep_all_k(const float* __restrict__ wpost, const float* __restrict__ wgc1,
                           const float* __restrict__ wgc2, const float* __restrict__ wqkv,
                           const float* __restrict__ wpw)
{
    int idx = blockIdx.x * blockDim.x + threadIdx.x;
    if (idx >= 167936) return;
    const float* src; int KK, base, li;
    if (idx < 36864)        { src = g_wl;   KK = 9; base = WT_L;    li = idx; }
    else if (idx < 73728)   { src = g_wgab; KK = 9; base = WT_GAB;  li = idx - 36864; }
    else if (idx < 110592)  { src = wpost;  KK = 9; base = WT_POST; li = idx - 73728; }
    else if (idx < 147456)  { src = wgc1;   KK = 9; base = WT_GC1;  li = idx - 110592; }
    else if (idx < 151552)  { src = wgc2;   KK = 1; base = WT_GC2;  li = idx - 147456; }
    else if (idx < 163840)  { src = wqkv;   KK = 1; base = WT_QKV;  li = idx - 151552; }
    else                    { src = wpw;    KK = 1; base = WT_PW;   li = idx - 163840; }
    int co = li / (64 * KK);
    int rem = li - co * (64 * KK);
    int ci = rem / KK, kp = rem - ci * KK;
    int cc = co >> 6, col = co & 63;
    int g = ci >> 3, cil = ci & 7;
    float v = src[li];
    __nv_bfloat16 h = __float2bfloat16(v);
    float lo = v - __bfloat162float(h);
    size_t o = (size_t)base + (((size_t)cc * 8 + g) * KK + kp) * 512 + col * 8 + cil;
    g_wPH[o] = bf_dup(v);
    g_wPL[o] = bf_dup(lo);
}

// ---------------- DFT matrices + fixed-A prep ----------------
__global__ void initdft_k()
{
    int idx = blockIdx.x * blockDim.x + threadIdx.x;
    if (idx >= NS * NS) return;
    int u = idx / NS, h = idx % NS;
    int m = (u * h) % NS;
    float xx = (2.0f * (float)m) / (float)NS;
    g_Cm[idx] = cospif(xx);
    g_Sm[idx] = sinpif(xx);
}

__global__ void prep_A_k()
{
    int idx = blockIdx.x * blockDim.x + threadIdx.x;
    if (idx >= 163840) return;
    float v = 0.f;
    if (idx < 16384) {                     // A1 = [Cm[0:64]; -Sm[0:64]]  [128][128]
        int m = idx >> 7, k = idx & 127;
        if (k < 126) v = (m < 64) ? g_Cm[m*NS + k] : -g_Sm[(m-64)*NS + k];
    } else if (idx < 81920) {              // A2 = [[Cm,Sm],[-Sm,Cm]]    [256][256]
        int li = idx - 16384; int m = li >> 8, k = li & 255;
        if (m < 252 && k < 252) {
            int qm = m >= 126, qk = k >= 126;
            int mm = qm ? m - 126 : m, kk = qk ? k - 126 : k;
            float c = g_Cm[mm*NS + kk], s = g_Sm[mm*NS + kk];
            v = (qm == qk) ? c : (qk ? s : -s);
        }
    } else if (idx < 147456) {             // A3 = [[Cm,-Sm],[Sm,Cm]]    [256][256]
        int li = idx - 81920; int m = li >> 8, k = li & 255;
        if (m < 252 && k < 252) {
            int qm = m >= 126, qk = k >= 126;
            int mm = qm ? m - 126 : m, kk = qk ? k - 126 : k;
            float c = g_Cm[mm*NS + kk], s = g_Sm[mm*NS + kk];
            v = (qm == qk) ? c : (qk ? -s : s);
        }
    } else {                               // A4 = [wgt.Cm[:,:64] | -wgt.Sm[:,:64]] [128][128]
        int li = idx - 147456; int m = li >> 7, k = li & 127;
        if (m < 126) {
            if (k < 64) {
                float w = (k == 0 || k == 63) ? 1.f : 2.f;
                v = w * g_Cm[m*NS + k];
            } else {
                int kk = k - 64;
                float w = (kk == 0 || kk == 63) ? 1.f : 2.f;
                v = -w * g_Sm[m*NS + kk];
            }
        }
    }
    __nv_bfloat16 h = __float2bfloat16(v);
    float lo = v - __bfloat162float(h);
    g_AH[idx] = bf_dup(v);
    g_AL[idx] = bf_dup(lo);
}

// ---------------- split-bf16 tensor-core GEMM for DFT stages ----------------
// C(M<=128 x N<=128 tile) = A(fixed, prepped hi/lo) x B(fp32 data, packed in-kernel)
// block: 256 thr = 8 warps all on M (8 x m16 = 128); NTILE = 64 (nt loop of 8).
// grid: (ceil(N/64), ceil(M/128), NIMG)
template<int MODE>
__global__ void __launch_bounds__(256)
gemm_dft(const uint32_t* __restrict__ AH, const uint32_t* __restrict__ AL,
         const float* __restrict__ B, int ldb, int kmax, int nmax, int bStride,
         int Kw, float* __restrict__ C,
         const float* __restrict__ xcIn, const float* __restrict__ gbw)
{
    __shared__ uint32_t sA[2][2][1024];   // [buf][plane][128 rows x 8 words]
    __shared__ float    sB[2][512];       // [buf][8 k x 64 n] fp32 staging
    __shared__ uint32_t sP[8 * 72];       // packed bf16x2, row stride 72 (==8 mod 32)

    int nb = blockIdx.x, mb = blockIdx.y, z = blockIdx.z;
    int tid = threadIdx.x;
    int warp = tid >> 5, lane = tid & 31;
    int gid = lane >> 2, tig = lane & 3;
    int m0 = warp * 16;
    int n0 = nb * 64;
    const float* Bz = B + (size_t)z * bStride;
    const uint32_t* AHb = AH + (size_t)(mb * 128) * Kw;
    const uint32_t* ALb = AL + (size_t)(mb * 128) * Kw;

    auto loadChunk = [&](int ch, int buf) {
        int kw0 = ch * 8;
        uint32_t ad = (uint32_t)__cvta_generic_to_shared(&sA[buf][0][0]);
        for (int t = tid; t < 512; t += 256) {
            int p = t >> 8, rr = (t >> 1) & 127, hh = t & 1;
            const uint32_t* src = (p ? ALb : AHb) + (size_t)rr * Kw + kw0 + hh * 4;
            uint32_t d = ad + (uint32_t)(((p * 128 + rr) * 8 + hh * 4) * 4);
            asm volatile("cp.async.ca.shared.global [%0], [%1], 16;" :: "r"(d), "l"(src));
        }
        uint32_t bd = (uint32_t)__cvta_generic_to_shared(&sB[buf][0]);
        for (int t = tid; t < 512; t += 256) {
            int kr = t >> 6, j = t & 63;
            int k = kw0 + kr, n = n0 + j;
            int valid = (k < kmax && n < nmax) ? 4 : 0;
            const float* gp = valid ? (Bz + (size_t)k * ldb + n) : Bz;
            uint32_t d = bd + (uint32_t)((kr * 64 + j) * 4);
            asm volatile("cp.async.ca.shared.global [%0], [%1], 4, %2;" :: "r"(d), "l"(gp), "r"(valid));
        }
        asm volatile("cp.async.commit_group;");
    };

    float acc[8][4];
#pragma unroll
    for (int nt = 0; nt < 8; nt++)
#pragma unroll
        for (int e = 0; e < 4; e++) acc[nt][e] = 0.f;

    int nk = Kw >> 3;
    loadChunk(0, 0);
    for (int ch = 0; ch < nk; ch++) {
        asm volatile("cp.async.wait_group 0;" ::: "memory");
        __syncthreads();
        {
            const float* ps = sB[ch & 1];
            for (int i = tid; i < 512; i += 256) {
                float v = ps[i];
                __nv_bfloat16 h = __float2bfloat16(v);
                float lo = v - __bfloat162float(h);
                __nv_bfloat16 l = __float2bfloat16(lo);
                int kr = i >> 6, j = i & 63;
                sP[kr * 72 + j] = (uint32_t)__bfloat16_as_ushort(h)
                                | ((uint32_t)__bfloat16_as_ushort(l) << 16);
            }
        }
        __syncthreads();
        if (ch + 1 < nk) loadChunk(ch + 1, (ch + 1) & 1);
        const uint32_t* AHs = &sA[ch & 1][0][0];
        const uint32_t* ALs = &sA[ch & 1][1][0];
        uint32_t ah0 = AHs[(m0 + gid) * 8 + tig];
        uint32_t ah1 = AHs[(m0 + gid + 8) * 8 + tig];
        uint32_t ah2 = AHs[(m0 + gid) * 8 + tig + 4];
        uint32_t ah3 = AHs[(m0 + gid + 8) * 8 + tig + 4];
        uint32_t al0 = ALs[(m0 + gid) * 8 + tig];
        uint32_t al1 = ALs[(m0 + gid + 8) * 8 + tig];
        uint32_t al2 = ALs[(m0 + gid) * 8 + tig + 4];
        uint32_t al3 = ALs[(m0 + gid + 8) * 8 + tig + 4];
#pragma unroll
        for (int nt = 0; nt < 8; nt++) {
            uint32_t b0 = sP[tig * 72 + nt * 8 + gid];
            uint32_t b1 = sP[(tig + 4) * 72 + nt * 8 + gid];
            asm volatile(
                "mma.sync.aligned.m16n8k16.row.col.f32.bf16.bf16.f32 "
                "{%0,%1,%2,%3}, {%4,%5,%6,%7}, {%8,%9}, {%0,%1,%2,%3};"
                : "+f"(acc[nt][0]), "+f"(acc[nt][1]), "+f"(acc[nt][2]), "+f"(acc[nt][3])
                : "r"(ah0), "r"(ah1), "r"(ah2), "r"(ah3), "r"(b0), "r"(b1));
            asm volatile(
                "mma.sync.aligned.m16n8k16.row.col.f32.bf16.bf16.f32 "
                "{%0,%1,%2,%3}, {%4,%5,%6,%7}, {%8,%9}, {%0,%1,%2,%3};"
                : "+f"(acc[nt][0]), "+f"(acc[nt][1]), "+f"(acc[nt][2]), "+f"(acc[nt][3])
                : "r"(al0), "r"(al1), "r"(al2), "r"(al3), "r"(b0), "r"(b1));
        }
        __syncthreads();
    }

    float fw0 = 0.f, fw1 = 0.f;
    if constexpr (MODE == 4) {
        float w0 = fmaxf(gbw[0], 0.f), w1 = fmaxf(gbw[1], 0.f);
        float d = w0 + w1 + 1e-8f;
        fw0 = (w0 / d) * (1.0f / (126.0f * 126.0f));
        fw1 = w1 / d;
    }
    int gmA = mb * 128 + m0 + gid;
#pragma unroll
    for (int nt = 0; nt < 8; nt++) {
#pragma unroll
        for (int e = 0; e < 4; e++) {
            int gm = gmA + ((e >= 2) ? 8 : 0);
            int gn = n0 + nt * 8 + 2 * tig + (e & 1);
            float v = acc[nt][e];
            if constexpr (MODE == 1) {
                // Y[gm<128][gn<126] -> YT[gn + (gm>=64?126:0)][gm&63]
                if (gn < 126) {
                    int drow = gn + ((gm >= 64) ? 126 : 0);
                    C[(size_t)z * 16128 + drow * 64 + (gm & 63)] = v;
                }
            } else if constexpr (MODE == 2) {
                if (gm < 252) C[(size_t)z * 16128 + gm * 64 + gn] = v;
            } else if constexpr (MODE == 3) {
                // C3[gm<252][gn<64] -> B4[gn + (gm>=126?64:0)][gm%126]
                if (gm < 252) {
                    int drow = gn + ((gm >= 126) ? 64 : 0);
                    int dcol = (gm >= 126) ? gm - 126 : gm;
                    C[(size_t)z * 16128 + drow * 126 + dcol] = v;
                }
            } else {
                if (gm < 126 && gn < 126) {
                    size_t o = (size_t)z * 15876 + gm * 126 + gn;
                    C[o] = fw0 * fabsf(v) + fw1 * xcIn[o];
                }
            }
        }
    }
}

// ---------------- high-pass mask on transposed-stacked spectrum ----------------
__global__ void maskT_k(float* __restrict__ zt)
{
    int idx = blockIdx.x * blockDim.x + threadIdx.x;
    if (idx >= NIMG * 126 * 64) return;
    int n = idx & 63;                 // u index
    int k = (idx >> 6) % 126;         // v index
    int z = idx / (126 * 64);
    size_t base = (size_t)z * 16128;
    float r = zt[base + k * 64 + n];
    float i = zt[base + (k + 126) * 64 + n];
    int su = (n < 63) ? n : n - 126;
    int sv = (k < 63) ? k : k - 126;
    float s = (su * su + sv * sv > 1600) ? sqrtf(r * r + i * i) : 0.f;
    zt[base + k * 64 + n] = r * s;
    zt[base + (k + 126) * 64 + n] = i * s;
}

// ---------------- tensor-core implicit-GEMM conv (split-bf16, exact dup-pair) ----
template<int K>
__global__ void __launch_bounds__(256)
conv_bf(const float* __restrict__ in, const uint32_t* __restrict__ wH,
        const uint32_t* __restrict__ wL,
        const float* __restrict__ bias, const float* __restrict__ bng,
        const float* __restrict__ bnb, float* __restrict__ out,
        int Hin, int Win, int CoutTotal, int coOff, int pad,
        int Hout, int Wout, int act)
{
    constexpr int KK = K * K;
    constexpr int RW = (K == 3) ? 132 : 136;
    constexpr int PSTR = (K == 3) ? 424 : 136;
    constexpr int ICH = 8 * PSTR;
    constexpr int WCH = KK * 512;
    constexpr int JW = (K == 3) ? 130 : 128;

    extern __shared__ uint32_t smemU[];
    uint32_t* sW  = smemU;
    float*    sSt = (float*)(smemU + 4 * WCH);
    uint32_t* sPk = smemU + 4 * WCH + 2 * ICH;

    int r0 = blockIdx.x;
    int cc = blockIdx.y;
    int b  = blockIdx.z;
    int tid = threadIdx.x;
    int warp = tid >> 5, lane = tid & 31;
    int wm = warp & 3, wn = warp >> 2;
    int gid = lane >> 2, tig = lane & 3;
    int m0 = wm * 16, n0 = wn * 64;

    const float* inb = in + (size_t)b * 64 * Hin * Win;
    const uint32_t* wHb = wH + (size_t)cc * (64 * 64 * KK);
    const uint32_t* wLb = wL + (size_t)cc * (64 * 64 * KK);

    auto loadGroup = [&](int g, int buf) {
        uint32_t wdst = (uint32_t)__cvta_generic_to_shared(&sW[buf * 2 * WCH]);
        const uint32_t* whs = wHb + (size_t)g * WCH;
        const uint32_t* wls = wLb + (size_t)g * WCH;
        for (int i = tid; i < WCH / 4; i += 256) {
            asm volatile("cp.async.cg.shared.global [%0], [%1], 16;"
                         :: "r"(wdst + i * 16), "l"(whs + i * 4));
            asm volatile("cp.async.cg.shared.global [%0], [%1], 16;"
                         :: "r"(wdst + (WCH + i * 4) * 4), "l"(wls + i * 4));
        }
        uint32_t idst = (uint32_t)__cvta_generic_to_shared(&sSt[buf * ICH]);
        int ci0 = g * 8;
        int total = 8 * K * JW;
        for (int t = tid; t < total; t += 256) {
            int ci = t / (K * JW);
            int rem = t - ci * (K * JW);
            int ky = rem / JW;
            int j = rem - ky * JW;
            int gy = r0 + ky - pad;
            int gx = j - pad;
            int valid = (gy >= 0 && gy < Hin && gx >= 0 && gx < Win) ? 4 : 0;
            const float* src = inb + (size_t)(ci0 + ci) * Hin * Win;
            const float* gp = valid ? (src + (size_t)gy * Win + gx) : src;
            uint32_t d = idst + (uint32_t)((ci * PSTR + ky * RW + j) * 4);
            asm volatile("cp.async.ca.shared.global [%0], [%1], 4, %2;"
                         :: "r"(d), "l"(gp), "r"(valid));
        }
        asm volatile("cp.async.commit_group;");
    };

    float acc[8][4];
#pragma unroll
    for (int nt = 0; nt < 8; nt++)
#pragma unroll
        for (int i = 0; i < 4; i++) acc[nt][i] = 0.f;

    loadGroup(0, 0);
    for (int g = 0; g < 8; g++) {
        asm volatile("cp.async.wait_group 0;" ::: "memory");
        __syncthreads();
        {
            const float* ps = &sSt[(g & 1) * ICH];
            for (int i = tid; i < ICH; i += 256) {
                float v = ps[i];
                __nv_bfloat16 h = __float2bfloat16(v);
                float lo = v - __bfloat162float(h);
                __nv_bfloat16 l = __float2bfloat16(lo);
                sPk[i] = (uint32_t)__bfloat16_as_ushort(h)
                       | ((uint32_t)__bfloat16_as_ushort(l) << 16);
            }
        }
        __syncthreads();
        if (g < 7) loadGroup(g + 1, (g + 1) & 1);
        const uint32_t* WHp = &sW[(g & 1) * 2 * WCH];
        const uint32_t* WLp = WHp + WCH;
#pragma unroll
        for (int kp = 0; kp < KK; kp++) {
            int ky = kp / K, kx = kp - ky * K;
            const uint32_t* wkh = WHp + kp * 512;
            const uint32_t* wkl = WLp + kp * 512;
            uint32_t ah0 = wkh[(m0 + gid) * 8 + tig];
            uint32_t ah1 = wkh[(m0 + gid + 8) * 8 + tig];
            uint32_t ah2 = wkh[(m0 + gid) * 8 + tig + 4];
            uint32_t ah3 = wkh[(m0 + gid + 8) * 8 + tig + 4];
            uint32_t al0 = wkl[(m0 + gid) * 8 + tig];
            uint32_t al1 = wkl[(m0 + gid + 8) * 8 + tig];
            uint32_t al2 = wkl[(m0 + gid) * 8 + tig + 4];
            uint32_t al3 = wkl[(m0 + gid + 8) * 8 + tig + 4];
            const uint32_t* pb0 = sPk + tig * PSTR + ky * RW + kx + n0 + gid;
            const uint32_t* pb1 = sPk + (tig + 4) * PSTR + ky * RW + kx + n0 + gid;
#pragma unroll
            for (int nt = 0; nt < 8; nt++) {
                uint32_t b0 = pb0[nt * 8];
                uint32_t b1 = pb1[nt * 8];
                asm volatile(
                    "mma.sync.aligned.m16n8k16.row.col.f32.bf16.bf16.f32 "
                    "{%0,%1,%2,%3}, {%4,%5,%6,%7}, {%8,%9}, {%0,%1,%2,%3};"
                    : "+f"(acc[nt][0]), "+f"(acc[nt][1]), "+f"(acc[nt][2]), "+f"(acc[nt][3])
                    : "r"(ah0), "r"(ah1), "r"(ah2), "r"(ah3), "r"(b0), "r"(b1));
                asm volatile(
                    "mma.sync.aligned.m16n8k16.row.col.f32.bf16.bf16.f32 "
                    "{%0,%1,%2,%3}, {%4,%5,%6,%7}, {%8,%9}, {%0,%1,%2,%3};"
                    : "+f"(acc[nt][0]), "+f"(acc[nt][1]), "+f"(acc[nt][2]), "+f"(acc[nt][3])
                    : "r"(al0), "r"(al1), "r"(al2), "r"(al3), "r"(b0), "r"(b1));
            }
        }
        __syncthreads();
    }

    int coA = cc * 64 + m0 + gid;
    int coB = coA + 8;
    float biA = bias ? bias[coA] : 0.f;
    float biB = bias ? bias[coB] : 0.f;
    float scA = 1.f, shA = 0.f, scB = 1.f, shB = 0.f;
    if (bng) {
        scA = bng[coA] * BN_SC; shA = bnb[coA];
        scB = bng[coB] * BN_SC; shB = bnb[coB];
    }
    size_t rowA = ((size_t)(b * CoutTotal + coOff + coA) * Hout + r0) * Wout;
    size_t rowB = ((size_t)(b * CoutTotal + coOff + coB) * Hout + r0) * Wout;
#pragma unroll
    for (int nt = 0; nt < 8; nt++) {
        int nb = n0 + nt * 8 + 2 * tig;
        if (nb >= Wout) continue;
        float v0 = acc[nt][0] + biA, v1 = acc[nt][1] + biA;
        float v2 = acc[nt][2] + biB, v3 = acc[nt][3] + biB;
        if (bng) {
            v0 = v0 * scA + shA; v1 = v1 * scA + shA;
            v2 = v2 * scB + shB; v3 = v3 * scB + shB;
        }
        if (act == 1) {
            v0 = fmaxf(v0, 0.f); v1 = fmaxf(v1, 0.f);
            v2 = fmaxf(v2, 0.f); v3 = fmaxf(v3, 0.f);
        } else if (act == 2) {
            v0 = fminf(fmaxf(v0, 0.f), 6.f); v1 = fminf(fmaxf(v1, 0.f), 6.f);
            v2 = fminf(fmaxf(v2, 0.f), 6.f); v3 = fminf(fmaxf(v3, 0.f), 6.f);
        }
        *(float2*)&out[rowA + nb] = make_float2(v0, v1);
        *(float2*)&out[rowB + nb] = make_float2(v2, v3);
    }
}

// ---------------- fp32 direct conv (kept for stride-2) ----------------
template<int K, int STRIDE>
__global__ void __launch_bounds__(256)
conv_t(const float* __restrict__ in, const float* __restrict__ w,
       const float* __restrict__ bias, const float* __restrict__ bng,
       const float* __restrict__ bnb, float* __restrict__ out,
       int Hin, int Win, int Cout, int CoutTotal, int coOff,
       int pad, int Hout, int Wout, int act, int accum)
{
    constexpr int KK = K * K;
    constexpr int TS = 32;
    constexpr int SPAN = (TS - 1) * STRIDE + K;
    constexpr int R = STRIDE + K;
    __shared__ __align__(16) float sW[64 * KK * 8];
    __shared__ float sIn1[SPAN * SPAN];

    int tileW = (Wout + TS - 1) / TS;
    int tX = blockIdx.x % tileW, tY = blockIdx.x / tileW;
    int ow0 = tX * TS, oh0 = tY * TS;
    int co0 = blockIdx.y << 3;
    int b   = blockIdx.z;
    int tid = threadIdx.x;
    int ty = tid >> 4, tx = tid & 15;

    for (int t = tid; t < 64 * KK * 8; t += 256) {
        int row = t >> 3, co = t & 7;
        int ci = row / KK, kp = row - ci * KK;
        sW[t] = (co0 + co < Cout) ? w[(size_t)(co0 + co) * (64 * KK) + ci * KK + kp] : 0.f;
    }

    int ih0 = oh0 * STRIDE - pad, iw0 = ow0 * STRIDE - pad;
    float acc[8][2][2];
#pragma unroll
    for (int co = 0; co < 8; co++)
#pragma unroll
        for (int oy = 0; oy < 2; oy++)
#pragma unroll
            for (int ox = 0; ox < 2; ox++) acc[co][oy][ox] = 0.f;

    const float* inb = in + (size_t)b * 64 * Hin * Win;
    int base = (ty * 2 * STRIDE) * SPAN + tx * 2 * STRIDE;

    for (int ci = 0; ci < 64; ci++) {
        __syncthreads();
        const float* ip = inb + (size_t)ci * Hin * Win;
        for (int t = tid; t < SPAN * SPAN; t += 256) {
            int iy = t / SPAN, ix = t - iy * SPAN;
            int gy = ih0 + iy, gx = iw0 + ix;
            sIn1[t] = (gy >= 0 && gy < Hin && gx >= 0 && gx < Win)
                          ? __ldg(&ip[(size_t)gy * Win + gx]) : 0.f;
        }
        __syncthreads();
        float xin[R][R];
#pragma unroll
        for (int r = 0; r < R; r++)
#pragma unroll
            for (int c = 0; c < R; c++) xin[r][c] = sIn1[base + r * SPAN + c];
        const float4* wq = reinterpret_cast<const float4*>(&sW[ci * KK * 8]);
#pragma unroll
        for (int kp = 0; kp < KK; kp++) {
            float4 wa = wq[kp * 2], wb = wq[kp * 2 + 1];
            float wv[8] = {wa.x, wa.y, wa.z, wa.w, wb.x, wb.y, wb.z, wb.w};
            int ky = kp / K, kx = kp - ky * K;
#pragma unroll
            for (int oy = 0; oy < 2; oy++)
#pragma unroll
                for (int ox = 0; ox < 2; ox++) {
                    float xv = xin[oy * STRIDE + ky][ox * STRIDE + kx];
#pragma unroll
                    for (int co = 0; co < 8; co++)
                        acc[co][oy][ox] += xv * wv[co];
                }
        }
    }

#pragma unroll
    for (int co = 0; co < 8; co++) {
        int gco = co0 + co;
        if (gco >= Cout) break;
        float bi = bias ? bias[gco] : 0.f;
        float sc = 1.f, sh = 0.f;
        if (bng) { sc = bng[gco] * BN_SC; sh = bnb[gco]; }
#pragma unroll
        for (int oy = 0; oy < 2; oy++) {
            int oh = oh0 + ty * 2 + oy;
            if (oh >= Hout) continue;
#pragma unroll
            for (int ox = 0; ox < 2; ox++) {
                int ow = ow0 + tx * 2 + ox;
                if (ow >= Wout) continue;
                float v = acc[co][oy][ox] + bi;
                if (bng) v = v * sc + sh;
                if (act == 1) v = fmaxf(v, 0.f);
                else if (act == 2) v = fminf(fmaxf(v, 0.f), 6.f);
                size_t oidx = (((size_t)b * CoutTotal + coOff + gco) * Hout + oh) * Wout + ow;
                if (accum) out[oidx] += v; else out[oidx] = v;
            }
        }
    }
}

// ---------------- maxpools ----------------
__global__ void mp21_k(const float* __restrict__ in, float* __restrict__ out)
{
    int idx = blockIdx.x * blockDim.x + threadIdx.x;
    int n = NIMG * 125 * 125;
    if (idx >= n) return;
    int w = idx % 125, h = (idx / 125) % 125, ch = idx / (125 * 125);
    const float* p = in + (size_t)ch * NS * NS + (size_t)h * NS + w;
    out[idx] = fmaxf(fmaxf(p[0], p[1]), fmaxf(p[NS], p[NS + 1]));
}
__global__ void mp22_k(const float* __restrict__ in, float* __restrict__ out)
{
    int idx = blockIdx.x * blockDim.x + threadIdx.x;
    int n = NIMG * 31 * 31;
    if (idx >= n) return;
    int w = idx % 31, h = (idx / 31) % 31, ch = idx / (31 * 31);
    const float* p = in + (size_t)ch * 62 * 62 + (size_t)(2 * h) * 62 + 2 * w;
    out[idx] = fmaxf(fmaxf(p[0], p[1]), fmaxf(p[62], p[63]));
}

// ---------------- bilinear resize 31 -> 128 ----------------
__global__ void resize_k(const float* __restrict__ in, float* __restrict__ out)
{
    int idx = blockIdx.x * blockDim.x + threadIdx.x;
    int n = NIMG * HW128 * HW128;
    if (idx >= n) return;
    int x = idx & 127, y = (idx >> 7) & 127, ch = idx >> 14;
    const float sc = 31.f / 128.f;
    float sy = fminf(fmaxf((y + 0.5f) * sc - 0.5f, 0.f), 30.f);
    float sx = fminf(fmaxf((x + 0.5f) * sc - 0.5f, 0.f), 30.f);
    int y0 = (int)floorf(sy); float fy = sy - y0; int y1 = min(y0 + 1, 30);
    int x0 = (int)floorf(sx); float fx = sx - x0; int x1 = min(x0 + 1, 30);
    const float* p = in + (size_t)ch * 961;
    float v = (1.f - fy) * ((1.f - fx) * p[y0 * 31 + x0] + fx * p[y0 * 31 + x1])
            + fy         * ((1.f - fx) * p[y1 * 31 + x0] + fx * p[y1 * 31 + x1]);
    out[idx] = v;
}

// ---------------- log_softmax over channels ----------------
__global__ void lsm_k(const float* __restrict__ in, float* __restrict__ out)
{
    int gid = blockIdx.x * blockDim.x + threadIdx.x;
    if (gid >= NB * HW128 * HW128) return;
    int b = gid >> 14, p = gid & 16383;
    size_t base = (size_t)b * NC * 16384 + p;
    float mx = -1e30f;
    for (int c = 0; c < NC; c++) mx = fmaxf(mx, in[base + (size_t)c * 16384]);
    float s = 0.f;
    for (int c = 0; c < NC; c++) s += expf(in[base + (size_t)c * 16384] - mx);
    float l = logf(s);
    for (int c = 0; c < NC; c++) {
        size_t o = base + (size_t)c * 16384;
        out[o] = in[o] - mx - l;
    }
}

// ---------------- windowed attention ----------------
__global__ void attn_k(const float* __restrict__ qkv, const float* __restrict__ rpb,
                       const int* __restrict__ relidx, float* __restrict__ o)
{
    __shared__ float sk[64][8];
    __shared__ float sv[64][8];
    int win = blockIdx.x;
    int gh = win >> 4, gw = win & 15;
    int n = blockIdx.y, b = blockIdx.z;
    int i = threadIdx.x;
    int hi = gh * 8 + (i >> 3), wi = gw * 8 + (i & 7);
    float q[8];
#pragma unroll
    for (int d = 0; d < 8; d++) {
        int cq = n * 8 + d;
        size_t sp = (size_t)hi * 128 + wi;
        q[d]      = qkv[(((size_t)b * 192 + cq)       * 16384) + sp];
        sk[i][d]  = qkv[(((size_t)b * 192 + 64 + cq)  * 16384) + sp];
        sv[i][d]  = qkv[(((size_t)b * 192 + 128 + cq) * 16384) + sp];
    }
    __syncthreads();
    float logits[64];
    float mx = -1e30f;
#pragma unroll
    for (int j = 0; j < 64; j++) {
        float dot = 0.f;
#pragma unroll
        for (int d = 0; d < 8; d++) dot += q[d] * sk[j][d];
        float l = dot * ATTN_SCALE + rpb[relidx[i * 64 + j] * 8 + n];
        logits[j] = l;
        mx = fmaxf(mx, l);
    }
    float se = 0.f;
#pragma unroll
    for (int j = 0; j < 64; j++) { float e = expf(logits[j] - mx); logits[j] = e; se += e; }
    float inv = 1.f / se;
    float od[8];
#pragma unroll
    for (int d = 0; d < 8; d++) od[d] = 0.f;
#pragma unroll
    for (int j = 0; j < 64; j++) {
#pragma unroll
        for (int d = 0; d < 8; d++) od[d] += logits[j] * sv[j][d];
    }
#pragma unroll
    for (int d = 0; d < 8; d++)
        o[(((size_t)b * 64 + n * 8 + d) * 128 + hi) * 128 + wi] = od[d] * inv;
}

// ---------------- directional pools + add local ----------------
__global__ void poolsum_k(const float* __restrict__ o, const float* __restrict__ loc,
                          float* __restrict__ out)
{
    int idx = blockIdx.x * blockDim.x + threadIdx.x;
    int n = NB * NC * HW128 * HW128;
    if (idx >= n) return;
    int w = idx & 127, h = (idx >> 7) & 127;
    size_t chbase = (size_t)(idx >> 14) * 16384;
    float sx = 0.f;
#pragma unroll
    for (int t = -3; t <= 4; t++) {
        int r = h + t;
        if (r >= 0 && r <= 128) { if (r == 128) r = 126; sx += o[chbase + (size_t)r * 128 + w]; }
    }
    float sy = 0.f;
#pragma unroll
    for (int t = -3; t <= 4; t++) {
        int c = w + t;
        if (c >= 0 && c <= 128) { if (c == 128) c = 126; sy += o[chbase + (size_t)h * 128 + c]; }
    }
    out[idx] = (sx + sy) * 0.125f + loc[idx];
}

// ---------------- depthwise 8x8 conv + BN ----------------
__global__ void dwconv_k(const float* __restrict__ in, const float* __restrict__ w,
                         const float* __restrict__ bng, const float* __restrict__ bnb,
                         float* __restrict__ out)
{
    __shared__ float sIn[23 * 23];
    __shared__ float sWt[64];
    int tile = blockIdx.x;
    int tX = tile & 7, tY = tile >> 3;
    int c = blockIdx.y, b = blockIdx.z;
    int tid = threadIdx.y * 16 + threadIdx.x;
    if (tid < 64) sWt[tid] = w[c * 64 + tid];
    int h0 = tY * 16 - 3, w0 = tX * 16 - 3;
    const float* ip = in + (size_t)(b * 64 + c) * 16384;
    for (int t = tid; t < 23 * 23; t += 256) {
        int iy = t / 23, ix = t - iy * 23;
        int gy = h0 + iy, gx = w0 + ix;
        sIn[t] = (gy >= 0 && gy < 128 && gx >= 0 && gx < 128) ? ip[(size_t)gy * 128 + gx] : 0.f;
    }
    __syncthreads();
    float acc = 0.f;
#pragma unroll
    for (int i = 0; i < 8; i++)
#pragma unroll
        for (int j = 0; j < 8; j++)
            acc += sIn[(threadIdx.y + i) * 23 + threadIdx.x + j] * sWt[i * 8 + j];
    float v = acc * (bng[c] * BN_SC) + bnb[c];
    out[((size_t)(b * 64 + c) * 128 + tY * 16 + threadIdx.y) * 128 + tX * 16 + threadIdx.x] = v;
}

// ---------------- host ----------------
extern "C" void kernel_launch(void* const* d_in, const int* in_sizes, int n_in,
                              void* d_out, int out_size)
{
    const float* x       = (const float*)d_in[0];
    const float* w_qkv   = (const float*)d_in[1];
    const float* w_l1    = (const float*)d_in[2];
    const float* gl1     = (const float*)d_in[3];
    const float* bl1     = (const float*)d_in[4];
    const float* w_l2    = (const float*)d_in[5];
    const float* gl2     = (const float*)d_in[6];
    const float* bl2     = (const float*)d_in[7];
    const float* f_cos   = (const float*)d_in[8];
    const float* f_sin   = (const float*)d_in[9];
    const float* gb_b1   = (const float*)d_in[10];
    const float* gb_b2   = (const float*)d_in[11];
    const float* gb_w    = (const float*)d_in[12];
    const float* w_post  = (const float*)d_in[13];
    const float* g_postp = (const float*)d_in[14];
    const float* b_postp = (const float*)d_in[15];
    const float* w_gc    = (const float*)d_in[16];
    const float* b_gc    = (const float*)d_in[17];
    const float* w_gc1   = (const float*)d_in[18];
    const float* b_gc1   = (const float*)d_in[19];
    const float* w_gc2   = (const float*)d_in[20];
    const float* b_gc2   = (const float*)d_in[21];
    const float* rpb     = (const float*)d_in[22];
    const float* w_dw    = (const float*)d_in[23];
    const float* g_proj  = (const float*)d_in[24];
    const float* b_proj  = (const float*)d_in[25];
    const float* w_pw    = (const float*)d_in[26];
    const int*   relidx  = (const int*)  d_in[27];
    float* out = (float*)d_out;

    float *loc, *qkv, *obuf, *sum, *dw, *xc, *xc2;
    float *pb, *qb, *rb, *sb, *tb, *ub, *vb, *dft1, *dft2, *dft3;
    uint32_t *wPH, *wPL, *AH, *AL;
    cudaGetSymbolAddress((void**)&loc,  g_local);
    cudaGetSymbolAddress((void**)&qkv,  g_qkv);
    cudaGetSymbolAddress((void**)&obuf, g_o);
    cudaGetSymbolAddress((void**)&sum,  g_sum);
    cudaGetSymbolAddress((void**)&dw,   g_dw);
    cudaGetSymbolAddress((void**)&xc,   g_xc);
    cudaGetSymbolAddress((void**)&xc2,  g_xc2);
    cudaGetSymbolAddress((void**)&pb,   g_p);
    cudaGetSymbolAddress((void**)&qb,   g_q);
    cudaGetSymbolAddress((void**)&rb,   g_r);
    cudaGetSymbolAddress((void**)&sb,   g_s);
    cudaGetSymbolAddress((void**)&tb,   g_t);
    cudaGetSymbolAddress((void**)&ub,   g_u);
    cudaGetSymbolAddress((void**)&vb,   g_v);
    cudaGetSymbolAddress((void**)&dft1, g_dft1);
    cudaGetSymbolAddress((void**)&dft2, g_dft2);
    cudaGetSymbolAddress((void**)&dft3, g_dft3);
    cudaGetSymbolAddress((void**)&wPH,  g_wPH);
    cudaGetSymbolAddress((void**)&wPL,  g_wPL);
    cudaGetSymbolAddress((void**)&AH,   g_AH);
    cudaGetSymbolAddress((void**)&AL,   g_AL);

    const int T = 256;
    const int SM3 = (4 * 9 * 512 + 3 * 8 * 424) * 4;   // 114,432 B
    const int SM1 = (4 * 1 * 512 + 3 * 8 * 136) * 4;   // 21,248 B
    cudaFuncSetAttribute(conv_bf<3>, cudaFuncAttributeMaxDynamicSharedMemorySize, SM3);
    cudaFuncSetAttribute(conv_bf<1>, cudaFuncAttributeMaxDynamicSharedMemorySize, SM1);

    // weight prep + DFT tables + DFT fixed matrices
    prep_l_k<<<(64*64*9 + T - 1)/T, T>>>(w_l1, gl1, bl1, w_l2, gl2, bl2);
    prep_gab_k<<<(64*64*9 + T - 1)/T, T>>>(f_cos, f_sin, gb_b1, gb_b2);
    prep_all_k<<<(167936 + T - 1)/T, T>>>(w_post, w_gc1, w_gc2, w_qkv, w_pw);
    initdft_k<<<(NS*NS + T - 1)/T, T>>>();
    prep_A_k<<<(163840 + T - 1)/T, T>>>();

    // local pre (merged l1+l2)
    conv_bf<3><<<dim3(128,1,NB), 256, SM3>>>(x, wPH + WT_L, wPL + WT_L, g_bl, nullptr, nullptr,
                                             loc, 128,128, 64,0, 1, 128,128, 0);
    // merged gabor conv (valid, 128->126)
    conv_bf<3><<<dim3(126,1,NB), 256, SM3>>>(loc, wPH + WT_GAB, wPL + WT_GAB, g_bgab, nullptr,
                                             nullptr, xc, 128,128, 64,0, 0, 126,126, 0);
    // DFT high-pass, all tensor-core split-bf16 GEMMs:
    // st1: [Yr;Yi] = A1 . X            -> YT (transposed-stacked)
    // st2: ZT = A2 . YT                -> ZT;  mask pass on ZT
    // st3: TT = A3 . ZT                -> B4 (scatter to [Tr;Ti])
    // st4: W  = A4 . B4 + combine epi  -> xc2
    gemm_dft<1><<<dim3(2,1,NIMG), 256>>>(AH + A1_OFF, AL + A1_OFF, xc, 126, 126, 126,
                                         NS*NS, 128, dft1, nullptr, nullptr);
    gemm_dft<2><<<dim3(1,2,NIMG), 256>>>(AH + A2_OFF, AL + A2_OFF, dft1, 64, 252, 64,
                                         16128, 256, dft2, nullptr, nullptr);
    maskT_k<<<(NIMG*126*64 + T - 1)/T, T>>>(dft2);
    gemm_dft<3><<<dim3(1,2,NIMG), 256>>>(AH + A3_OFF, AL + A3_OFF, dft2, 64, 252, 64,
                                         16128, 256, dft3, nullptr, nullptr);
    gemm_dft<4><<<dim3(2,1,NIMG), 256>>>(AH + A4_OFF, AL + A4_OFF, dft3, 126, 128, 126,
                                         16128, 128, xc2, xc, gb_w);
    // post conv + bn + relu6
    conv_bf<3><<<dim3(126,1,NB), 256, SM3>>>(xc2, wPH + WT_POST, wPL + WT_POST, nullptr,
                                             g_postp, b_postp, pb, 126,126, 64,0, 1, 126,126, 2);
    mp21_k<<<(NIMG*125*125 + T - 1)/T, T>>>(pb, qb);
    conv_t<3,2><<<dim3(4, 8, NB), T>>>(qb, w_gc, b_gc, nullptr, nullptr, rb,
                                       125,125, 64,64,0, 0, 62,62, 1,0);
    mp22_k<<<(NIMG*31*31 + T - 1)/T, T>>>(rb, sb);
    resize_k<<<(NIMG*16384 + T - 1)/T, T>>>(sb, tb);
    conv_bf<3><<<dim3(128,1,NB), 256, SM3>>>(tb, wPH + WT_GC1, wPL + WT_GC1, b_gc1, nullptr,
                                             nullptr, ub, 128,128, 64,0, 1, 128,128, 1);
    conv_bf<1><<<dim3(128,1,NB), 256, SM1>>>(ub, wPH + WT_GC2, wPL + WT_GC2, b_gc2, nullptr,
                                             nullptr, vb, 128,128, 64,0, 0, 128,128, 0);
    lsm_k<<<(NB*16384 + T - 1)/T, T>>>(vb, loc);
    // global branch
    conv_bf<1><<<dim3(128,3,NB), 256, SM1>>>(x, wPH + WT_QKV, wPL + WT_QKV, nullptr, nullptr,
                                             nullptr, qkv, 128,128, 192,0, 0, 128,128, 0);
    attn_k<<<dim3(256, NH_, NB), 64>>>(qkv, rpb, relidx, obuf);
    poolsum_k<<<(NB*NC*16384 + T - 1)/T, T>>>(obuf, loc, sum);
    dwconv_k<<<dim3(64, 64, NB), dim3(16,16)>>>(sum, w_dw, g_proj, b_proj, dw);
    conv_bf<1><<<dim3(128,1,NB), 256, SM1>>>(dw, wPH + WT_PW, wPL + WT_PW, nullptr, nullptr,
                                             nullptr, out, 128,128, 64,0, 0, 128,128, 0);
    (void)in_sizes; (void)n_in; (void)out_size;
}